// round 4
// baseline (speedup 1.0000x reference)
#include <cuda_runtime.h>
#include <cuda_bf16.h>
#include <cstdint>
#include <math.h>

// Problem constants
#define B_  4
#define S_  2048
#define E_  1024
#define H_  16
#define HD_ 64
#define BH_ (B_*H_)           // 64
#define N3E (3*E_)            // 3072
#define MROWS (B_*S_)         // 8192

// ---------------- scratch (device globals; allocation-free) ----------------
__device__ float g_q[(size_t)BH_ * S_ * HD_];     // [B,H,S,HD]
__device__ float g_k[(size_t)BH_ * S_ * HD_];
__device__ float g_v[(size_t)BH_ * S_ * HD_];
__device__ float g_vals[(size_t)B_ * S_ * E_];    // [B,S,E]

// split-bf16 operands
__device__ __nv_bfloat16 g_xh[(size_t)MROWS * E_];
__device__ __nv_bfloat16 g_xl[(size_t)MROWS * E_];
__device__ __nv_bfloat16 g_wqkvT_h[(size_t)N3E * E_];   // [N=3072][K=1024]
__device__ __nv_bfloat16 g_wqkvT_l[(size_t)N3E * E_];
__device__ __nv_bfloat16 g_woT_h[(size_t)E_ * E_];      // [N=1024][K=1024]
__device__ __nv_bfloat16 g_woT_l[(size_t)E_ * E_];
__device__ __nv_bfloat16 g_vh[(size_t)MROWS * E_];
__device__ __nv_bfloat16 g_vl[(size_t)MROWS * E_];

// ---------------- helpers ----------------
__device__ __forceinline__ uint32_t smem_u32(const void* p) {
    uint32_t a;
    asm("{ .reg .u64 t; cvta.to.shared.u64 t, %1; cvt.u32.u64 %0, t; }"
        : "=r"(a) : "l"(p));
    return a;
}

__device__ __forceinline__ void ldsm_x4(uint32_t& r0, uint32_t& r1,
                                        uint32_t& r2, uint32_t& r3, uint32_t addr) {
    asm volatile("ldmatrix.sync.aligned.m8n8.x4.shared.b16 {%0,%1,%2,%3}, [%4];"
                 : "=r"(r0), "=r"(r1), "=r"(r2), "=r"(r3) : "r"(addr));
}

__device__ __forceinline__ void mma_bf16(float& c0, float& c1, float& c2, float& c3,
                                         uint32_t a0, uint32_t a1, uint32_t a2, uint32_t a3,
                                         uint32_t b0, uint32_t b1) {
    asm volatile(
        "mma.sync.aligned.m16n8k16.row.col.f32.bf16.bf16.f32 "
        "{%0,%1,%2,%3}, {%4,%5,%6,%7}, {%8,%9}, {%0,%1,%2,%3};"
        : "+f"(c0), "+f"(c1), "+f"(c2), "+f"(c3)
        : "r"(a0), "r"(a1), "r"(a2), "r"(a3), "r"(b0), "r"(b1));
}

// ---------------------------------------------------------------------------
// split kernels: fp32 -> (hi, lo) bf16
// ---------------------------------------------------------------------------
__global__ void __launch_bounds__(256) split_f32_kernel(
    const float* __restrict__ X, __nv_bfloat16* __restrict__ Xh,
    __nv_bfloat16* __restrict__ Xl, int n4)
{
    int i = blockIdx.x * blockDim.x + threadIdx.x;
    if (i >= n4) return;
    float4 v = ((const float4*)X)[i];
    __nv_bfloat16 h0 = __float2bfloat16(v.x), h1 = __float2bfloat16(v.y);
    __nv_bfloat16 h2 = __float2bfloat16(v.z), h3 = __float2bfloat16(v.w);
    __nv_bfloat16 l0 = __float2bfloat16(v.x - __bfloat162float(h0));
    __nv_bfloat16 l1 = __float2bfloat16(v.y - __bfloat162float(h1));
    __nv_bfloat16 l2 = __float2bfloat16(v.z - __bfloat162float(h2));
    __nv_bfloat16 l3 = __float2bfloat16(v.w - __bfloat162float(h3));
    ((__nv_bfloat162*)Xh)[2*i]   = __nv_bfloat162(h0, h1);
    ((__nv_bfloat162*)Xh)[2*i+1] = __nv_bfloat162(h2, h3);
    ((__nv_bfloat162*)Xl)[2*i]   = __nv_bfloat162(l0, l1);
    ((__nv_bfloat162*)Xl)[2*i+1] = __nv_bfloat162(l2, l3);
}

// W[K][N] (row-major, N contiguous) -> Th/Tl [N][K] (K contiguous), split bf16
__global__ void __launch_bounds__(256) split_wT_kernel(
    const float* __restrict__ W, __nv_bfloat16* __restrict__ Th,
    __nv_bfloat16* __restrict__ Tl, int Kdim, int Ndim)
{
    __shared__ float t[32][33];
    int n0 = blockIdx.x * 32, k0 = blockIdx.y * 32;
    int tx = threadIdx.x, ty = threadIdx.y;   // 32 x 8
    #pragma unroll
    for (int i = ty; i < 32; i += 8)
        t[i][tx] = W[(size_t)(k0 + i) * Ndim + n0 + tx];
    __syncthreads();
    #pragma unroll
    for (int i = ty; i < 32; i += 8) {
        float v = t[tx][i];                   // = W[k0+tx][n0+i]
        __nv_bfloat16 h = __float2bfloat16(v);
        __nv_bfloat16 l = __float2bfloat16(v - __bfloat162float(h));
        Th[(size_t)(n0 + i) * Kdim + k0 + tx] = h;
        Tl[(size_t)(n0 + i) * Kdim + k0 + tx] = l;
    }
}

// ---------------------------------------------------------------------------
// mma.sync split-bf16 GEMM: C[128,128] = A[128,1024] @ B[128,1024]^T
//   C = Ah@Bh + Ah@Bl + Al@Bh  (fp32 accumulate)
// mode 0: A = x, B = w_qkvT, epilogue scatters into g_q/g_k/g_v + bias
// mode 1: A = vals, B = w_oT, epilogue writes Cout + bias
// 256 threads = 8 warps (4 m-groups x 2 n-groups); warp tile 32x64.
// ---------------------------------------------------------------------------
#define GK    1024
#define BK    64
#define PITCH 72           // smem row pitch in bf16 elems (144B, bank-rotating)
#define TILE_B (128 * PITCH * 2)            // 18432 bytes per tile
#define GEMM_SMEM (4 * TILE_B)              // 73728 bytes

__global__ void __launch_bounds__(256) mma_gemm_kernel(
    const float* __restrict__ bias, float* __restrict__ Cout, int Ntot, int mode)
{
    extern __shared__ char smem[];
    const uint32_t sA_h = smem_u32(smem);
    const uint32_t sA_l = sA_h + TILE_B;
    const uint32_t sB_h = sA_h + 2*TILE_B;
    const uint32_t sB_l = sA_h + 3*TILE_B;

    const int tid = threadIdx.x;
    const int wid = tid >> 5, lane = tid & 31;
    const int wm = wid & 3;          // m-group: rows wm*32..wm*32+31
    const int wn = wid >> 2;         // n-group: cols wn*64..wn*64+63
    const int bx = blockIdx.x, by = blockIdx.y;

    const __nv_bfloat16 *Ah, *Al, *Bh, *Bl;
    if (mode == 0) { Ah = g_xh; Al = g_xl; Bh = g_wqkvT_h; Bl = g_wqkvT_l; }
    else           { Ah = g_vh; Al = g_vl; Bh = g_woT_h;   Bl = g_woT_l;   }

    const size_t aBase = (size_t)(by * 128) * GK;
    const size_t bBase = (size_t)(bx * 128) * GK;

    float acc[2][8][4];
    #pragma unroll
    for (int mf = 0; mf < 2; mf++)
        #pragma unroll
        for (int nf = 0; nf < 8; nf++)
            #pragma unroll
            for (int e = 0; e < 4; e++) acc[mf][nf][e] = 0.f;

    // ldmatrix per-lane address components
    const int l7 = lane & 7;
    const int aRowOff = ((lane >> 3) & 1) * 8 + l7;   // row within 16-row frag
    const int aKOff   = (lane >> 4) * 8;              // 0 or 8
    const int bRowOff = ((lane >> 4) & 1) * 8 + l7;   // n-row within 16
    const int bKOff   = ((lane >> 3) & 1) * 8;        // 0 or 8

    for (int kc = 0; kc < GK / BK; kc++) {
        const int kOff = kc * BK;
        // ---- load 4 tiles (128 x 64 bf16 each) ----
        {
            const __nv_bfloat16* srcs[4] = {
                Ah + aBase + kOff, Al + aBase + kOff,
                Bh + bBase + kOff, Bl + bBase + kOff };
            #pragma unroll
            for (int t = 0; t < 4; t++) {
                const __nv_bfloat16* src = srcs[t];
                const uint32_t dst = sA_h + t * TILE_B;
                for (int i = tid; i < 1024; i += 256) {
                    int r = i >> 3;
                    int c = (i & 7) * 8;
                    int4 v = *(const int4*)(src + (size_t)r * GK + c);
                    asm volatile("st.shared.v4.b32 [%0], {%1,%2,%3,%4};" ::
                        "r"(dst + (uint32_t)(r * PITCH + c) * 2),
                        "r"(v.x), "r"(v.y), "r"(v.z), "r"(v.w) : "memory");
                }
            }
        }
        __syncthreads();

        #pragma unroll
        for (int ks = 0; ks < 4; ks++) {
            const int kcol = ks * 16;
            // A fragments (hi & lo), 2 m16 frags each
            uint32_t ah[2][4], al[2][4];
            #pragma unroll
            for (int mf = 0; mf < 2; mf++) {
                uint32_t off = (uint32_t)((wm*32 + mf*16 + aRowOff) * PITCH
                                          + kcol + aKOff) * 2;
                ldsm_x4(ah[mf][0], ah[mf][1], ah[mf][2], ah[mf][3], sA_h + off);
                ldsm_x4(al[mf][0], al[mf][1], al[mf][2], al[mf][3], sA_l + off);
            }
            // n in two halves of 32 to bound register pressure
            #pragma unroll
            for (int nh = 0; nh < 2; nh++) {
                uint32_t bh[4][2], bl[4][2];
                #pragma unroll
                for (int g = 0; g < 2; g++) {   // covers n16 per x4 load
                    uint32_t off = (uint32_t)((wn*64 + nh*32 + g*16 + bRowOff) * PITCH
                                              + kcol + bKOff) * 2;
                    ldsm_x4(bh[g*2][0], bh[g*2][1], bh[g*2+1][0], bh[g*2+1][1],
                            sB_h + off);
                    ldsm_x4(bl[g*2][0], bl[g*2][1], bl[g*2+1][0], bl[g*2+1][1],
                            sB_l + off);
                }
                #pragma unroll
                for (int mf = 0; mf < 2; mf++)
                    #pragma unroll
                    for (int nn = 0; nn < 4; nn++) {
                        float* c = acc[mf][nh*4 + nn];
                        mma_bf16(c[0], c[1], c[2], c[3],
                                 ah[mf][0], ah[mf][1], ah[mf][2], ah[mf][3],
                                 bh[nn][0], bh[nn][1]);
                        mma_bf16(c[0], c[1], c[2], c[3],
                                 ah[mf][0], ah[mf][1], ah[mf][2], ah[mf][3],
                                 bl[nn][0], bl[nn][1]);
                        mma_bf16(c[0], c[1], c[2], c[3],
                                 al[mf][0], al[mf][1], al[mf][2], al[mf][3],
                                 bh[nn][0], bh[nn][1]);
                    }
            }
        }
        __syncthreads();
    }

    // ---- epilogue ----
    const int g = lane >> 2, cq = lane & 3;
    #pragma unroll
    for (int mf = 0; mf < 2; mf++) {
        #pragma unroll
        for (int nf = 0; nf < 8; nf++) {
            const int n = bx*128 + wn*64 + nf*8 + 2*cq;
            const float b0 = bias[n], b1 = bias[n+1];
            #pragma unroll
            for (int half = 0; half < 2; half++) {
                const int m = by*128 + wm*32 + mf*16 + g + half*8;
                float2 v2;
                v2.x = acc[mf][nf][half*2 + 0] + b0;
                v2.y = acc[mf][nf][half*2 + 1] + b1;
                if (mode == 0) {
                    const int bb = m >> 11, s = m & 2047;
                    const int h = n / 192;
                    const int rr = n - h * 192;
                    const size_t base = (((size_t)bb * H_ + h) * S_ + s) * HD_;
                    if (rr < 64)       *(float2*)&g_q[base + rr]       = v2;
                    else if (rr < 128) *(float2*)&g_k[base + rr - 64]  = v2;
                    else               *(float2*)&g_v[base + rr - 128] = v2;
                } else {
                    *(float2*)&Cout[(size_t)m * Ntot + n] = v2;
                }
            }
        }
    }
}

// ---------------------------------------------------------------------------
// FUSED attention: logits + online softmax + probs + p@V (unchanged from R2)
// ---------------------------------------------------------------------------
__global__ void __launch_bounds__(256) attn_fused_kernel(float* __restrict__ attn)
{
    const int head = blockIdx.y;
    const int qt   = (int)gridDim.x - 1 - (int)blockIdx.x;

    const float* qbase = g_q + (size_t)head*S_*HD_;
    const float* kbase = g_k + (size_t)head*S_*HD_;
    const float* vbase = g_v + (size_t)head*S_*HD_;
    float* out = attn + (size_t)head*S_*S_;

    const int tid = threadIdx.x;
    const int ty = tid >> 4, tx = tid & 15;

    __shared__ float Qs[64][68];
    __shared__ float Ks[64][68];
    __shared__ float msnap[32][64];

    {
        const int c0 = (qt + 1) * 64;
        const int nc = S_ - c0;
        if (nc > 0) {
            const int n4 = nc >> 2;
            const float4 z = make_float4(0.f, 0.f, 0.f, 0.f);
            for (int idx = tid; idx < 64 * n4; idx += 256) {
                int r = idx / n4;
                int c = (idx - r * n4) << 2;
                *(float4*)&out[(size_t)(qt*64 + r)*S_ + c0 + c] = z;
            }
        }
    }

    for (int idx = tid; idx < 64*16; idx += 256) {
        int r = idx >> 4;
        int c = (idx & 15) * 4;
        float4 q4 = *(const float4*)&qbase[(size_t)(qt*64 + r)*HD_ + c];
        Qs[c+0][r] = q4.x; Qs[c+1][r] = q4.y; Qs[c+2][r] = q4.z; Qs[c+3][r] = q4.w;
    }

    float m_run[4], s_run[4];
    #pragma unroll
    for (int i = 0; i < 4; i++) { m_run[i] = -INFINITY; s_run[i] = 0.f; }

    const float scale = 0.125f;

    for (int kt = 0; kt <= qt; kt++) {
        __syncthreads();
        for (int idx = tid; idx < 64*16; idx += 256) {
            int r = idx >> 4;
            int c = (idx & 15) * 4;
            float4 k4 = *(const float4*)&kbase[(size_t)(kt*64 + r)*HD_ + c];
            Ks[c+0][r] = k4.x; Ks[c+1][r] = k4.y; Ks[c+2][r] = k4.z; Ks[c+3][r] = k4.w;
        }
        __syncthreads();

        float acc[4][4];
        #pragma unroll
        for (int i = 0; i < 4; i++)
            #pragma unroll
            for (int j = 0; j < 4; j++) acc[i][j] = 0.f;

        #pragma unroll 4
        for (int k = 0; k < 64; k++) {
            float4 a = *(float4*)&Qs[k][ty*4];
            float4 b = *(float4*)&Ks[k][tx*4];
            acc[0][0] = fmaf(a.x,b.x,acc[0][0]); acc[0][1] = fmaf(a.x,b.y,acc[0][1]);
            acc[0][2] = fmaf(a.x,b.z,acc[0][2]); acc[0][3] = fmaf(a.x,b.w,acc[0][3]);
            acc[1][0] = fmaf(a.y,b.x,acc[1][0]); acc[1][1] = fmaf(a.y,b.y,acc[1][1]);
            acc[1][2] = fmaf(a.y,b.z,acc[1][2]); acc[1][3] = fmaf(a.y,b.w,acc[1][3]);
            acc[2][0] = fmaf(a.z,b.x,acc[2][0]); acc[2][1] = fmaf(a.z,b.y,acc[2][1]);
            acc[2][2] = fmaf(a.z,b.z,acc[2][2]); acc[2][3] = fmaf(a.z,b.w,acc[2][3]);
            acc[3][0] = fmaf(a.w,b.x,acc[3][0]); acc[3][1] = fmaf(a.w,b.y,acc[3][1]);
            acc[3][2] = fmaf(a.w,b.z,acc[3][2]); acc[3][3] = fmaf(a.w,b.w,acc[3][3]);
        }

        const bool diag = (kt == qt);
        #pragma unroll
        for (int i = 0; i < 4; i++) {
            const int row = qt*64 + ty*4 + i;
            float l[4]; bool valid[4];
            #pragma unroll
            for (int j = 0; j < 4; j++) {
                int col = kt*64 + tx*4 + j;
                l[j] = acc[i][j] * scale;
                valid[j] = !diag || (col <= row);
            }
            float t = -INFINITY;
            #pragma unroll
            for (int j = 0; j < 4; j++) t = fmaxf(t, valid[j] ? l[j] : -INFINITY);
            #pragma unroll
            for (int o = 8; o > 0; o >>= 1)
                t = fmaxf(t, __shfl_xor_sync(0xffffffffu, t, o));
            float m_new = fmaxf(m_run[i], t);

            float e[4], rs = 0.f;
            #pragma unroll
            for (int j = 0; j < 4; j++) {
                e[j] = valid[j] ? __expf(l[j] - m_new) : 0.f;
                rs += e[j];
            }
            *(float4*)&out[(size_t)row*S_ + kt*64 + tx*4] =
                make_float4(e[0], e[1], e[2], e[3]);
            #pragma unroll
            for (int o = 8; o > 0; o >>= 1)
                rs += __shfl_xor_sync(0xffffffffu, rs, o);

            s_run[i] = s_run[i] * __expf(m_run[i] - m_new) + rs;
            m_run[i] = m_new;
            if (tx == 0) msnap[kt][ty*4 + i] = m_new;
        }
    }

    float inv_s[4], mf[4];
    #pragma unroll
    for (int i = 0; i < 4; i++) { inv_s[i] = 1.f / s_run[i]; mf[i] = m_run[i]; }

    float vacc[4][4];
    #pragma unroll
    for (int i = 0; i < 4; i++)
        #pragma unroll
        for (int j = 0; j < 4; j++) vacc[i][j] = 0.f;

    for (int kt = 0; kt <= qt; kt++) {
        __syncthreads();
        for (int idx = tid; idx < 64*16; idx += 256) {
            int r = idx >> 4;
            int c = (idx & 15) * 4;
            *(float4*)&Ks[r][c] = *(const float4*)&vbase[(size_t)(kt*64 + r)*HD_ + c];
        }
        #pragma unroll
        for (int i = 0; i < 4; i++) {
            const int row = qt*64 + ty*4 + i;
            float4 e4 = *(float4*)&out[(size_t)row*S_ + kt*64 + tx*4];
            float f = __expf(msnap[kt][ty*4 + i] - mf[i]) * inv_s[i];
            e4.x *= f; e4.y *= f; e4.z *= f; e4.w *= f;
            *(float4*)&out[(size_t)row*S_ + kt*64 + tx*4] = e4;
            *(float4*)&Qs[ty*4 + i][tx*4] = e4;
        }
        __syncthreads();

        #pragma unroll 4
        for (int k = 0; k < 64; k++) {
            float a0 = Qs[ty*4+0][k];
            float a1 = Qs[ty*4+1][k];
            float a2 = Qs[ty*4+2][k];
            float a3 = Qs[ty*4+3][k];
            float4 b = *(float4*)&Ks[k][tx*4];
            vacc[0][0] = fmaf(a0,b.x,vacc[0][0]); vacc[0][1] = fmaf(a0,b.y,vacc[0][1]);
            vacc[0][2] = fmaf(a0,b.z,vacc[0][2]); vacc[0][3] = fmaf(a0,b.w,vacc[0][3]);
            vacc[1][0] = fmaf(a1,b.x,vacc[1][0]); vacc[1][1] = fmaf(a1,b.y,vacc[1][1]);
            vacc[1][2] = fmaf(a1,b.z,vacc[1][2]); vacc[1][3] = fmaf(a1,b.w,vacc[1][3]);
            vacc[2][0] = fmaf(a2,b.x,vacc[2][0]); vacc[2][1] = fmaf(a2,b.y,vacc[2][1]);
            vacc[2][2] = fmaf(a2,b.z,vacc[2][2]); vacc[2][3] = fmaf(a2,b.w,vacc[2][3]);
            vacc[3][0] = fmaf(a3,b.x,vacc[3][0]); vacc[3][1] = fmaf(a3,b.y,vacc[3][1]);
            vacc[3][2] = fmaf(a3,b.z,vacc[3][2]); vacc[3][3] = fmaf(a3,b.w,vacc[3][3]);
        }
    }

    const int bb = head >> 4, h = head & 15;
    #pragma unroll
    for (int i = 0; i < 4; i++) {
        int s = qt*64 + ty*4 + i;
        *(float4*)&g_vals[((size_t)bb*S_ + s)*E_ + h*HD_ + tx*4] =
            make_float4(vacc[i][0], vacc[i][1], vacc[i][2], vacc[i][3]);
    }
}

// ---------------------------------------------------------------------------
extern "C" void kernel_launch(void* const* d_in, const int* in_sizes, int n_in,
                              void* d_out, int out_size)
{
    const float* x     = (const float*)d_in[0];   // [B,S,E]
    const float* w_qkv = (const float*)d_in[1];   // [E,3E]
    const float* b_qkv = (const float*)d_in[2];   // [3E]
    const float* w_o   = (const float*)d_in[3];   // [E,E]
    const float* b_o   = (const float*)d_in[4];   // [E]
    // d_in[5] = causal mask (hardcoded)

    float* o_out    = (float*)d_out;                       // [B,S,E]
    float* attn_out = o_out + (size_t)B_ * S_ * E_;        // [B,H,S,S]

    static bool attr_set = false;
    if (!attr_set) {
        cudaFuncSetAttribute(mma_gemm_kernel,
                             cudaFuncAttributeMaxDynamicSharedMemorySize, GEMM_SMEM);
        attr_set = true;
    }

    __nv_bfloat16 *p_xh, *p_xl, *p_wqh, *p_wql, *p_woh, *p_wol, *p_vh, *p_vl;
    cudaGetSymbolAddress((void**)&p_xh,  g_xh);
    cudaGetSymbolAddress((void**)&p_xl,  g_xl);
    cudaGetSymbolAddress((void**)&p_wqh, g_wqkvT_h);
    cudaGetSymbolAddress((void**)&p_wql, g_wqkvT_l);
    cudaGetSymbolAddress((void**)&p_woh, g_woT_h);
    cudaGetSymbolAddress((void**)&p_wol, g_woT_l);
    cudaGetSymbolAddress((void**)&p_vh,  g_vh);
    cudaGetSymbolAddress((void**)&p_vl,  g_vl);
    float* p_vals;
    cudaGetSymbolAddress((void**)&p_vals, g_vals);

    // 0. split inputs to bf16 hi/lo
    {
        int n4 = (MROWS * E_) / 4;
        split_f32_kernel<<<n4 / 256, 256>>>(x, p_xh, p_xl, n4);
        dim3 g1(N3E/32, E_/32);
        split_wT_kernel<<<g1, dim3(32,8)>>>(w_qkv, p_wqh, p_wql, E_, N3E);
        dim3 g2(E_/32, E_/32);
        split_wT_kernel<<<g2, dim3(32,8)>>>(w_o, p_woh, p_wol, E_, E_);
    }
    // 1. QKV projection (tensor cores via mma.sync) + scatter
    {
        dim3 grid(N3E/128, MROWS/128);                 // (24, 64)
        mma_gemm_kernel<<<grid, 256, GEMM_SMEM>>>(b_qkv, nullptr, N3E, 0);
    }
    // 2. fused attention
    {
        dim3 grid(S_/64, BH_);
        attn_fused_kernel<<<grid, 256>>>(attn_out);
    }
    // 3. split vals, output projection (tensor cores via mma.sync)
    {
        int n4 = (MROWS * E_) / 4;
        split_f32_kernel<<<n4 / 256, 256>>>(p_vals, p_vh, p_vl, n4);
        dim3 grid(E_/128, MROWS/128);                  // (8, 64)
        mma_gemm_kernel<<<grid, 256, GEMM_SMEM>>>(b_o, o_out, E_, 1);
    }
}

// round 5
// speedup vs baseline: 1.5990x; 1.5990x over previous
#include <cuda_runtime.h>
#include <cuda_bf16.h>
#include <cstdint>
#include <math.h>

// Problem constants
#define B_  4
#define S_  2048
#define E_  1024
#define H_  16
#define HD_ 64
#define BH_ (B_*H_)           // 64
#define N3E (3*E_)            // 3072
#define MROWS (B_*S_)         // 8192

// ---------------- scratch (device globals; allocation-free) ----------------
__device__ float g_q[(size_t)BH_ * S_ * HD_];     // [B,H,S,HD]
__device__ float g_k[(size_t)BH_ * S_ * HD_];
__device__ float g_v[(size_t)BH_ * S_ * HD_];
__device__ float g_vals[(size_t)B_ * S_ * E_];    // [B,S,E]

// split-bf16 operands
__device__ __nv_bfloat16 g_xh[(size_t)MROWS * E_];
__device__ __nv_bfloat16 g_xl[(size_t)MROWS * E_];
__device__ __nv_bfloat16 g_wqkvT_h[(size_t)N3E * E_];   // [N=3072][K=1024]
__device__ __nv_bfloat16 g_wqkvT_l[(size_t)N3E * E_];
__device__ __nv_bfloat16 g_woT_h[(size_t)E_ * E_];      // [N=1024][K=1024]
__device__ __nv_bfloat16 g_woT_l[(size_t)E_ * E_];
__device__ __nv_bfloat16 g_vh[(size_t)MROWS * E_];
__device__ __nv_bfloat16 g_vl[(size_t)MROWS * E_];

// ---------------- helpers ----------------
__device__ __forceinline__ uint32_t smem_u32(const void* p) {
    uint32_t a;
    asm("{ .reg .u64 t; cvta.to.shared.u64 t, %1; cvt.u32.u64 %0, t; }"
        : "=r"(a) : "l"(p));
    return a;
}

__device__ __forceinline__ void ldsm_x4(uint32_t& r0, uint32_t& r1,
                                        uint32_t& r2, uint32_t& r3, uint32_t addr) {
    asm volatile("ldmatrix.sync.aligned.m8n8.x4.shared.b16 {%0,%1,%2,%3}, [%4];"
                 : "=r"(r0), "=r"(r1), "=r"(r2), "=r"(r3) : "r"(addr));
}

__device__ __forceinline__ void mma_bf16(float& c0, float& c1, float& c2, float& c3,
                                         uint32_t a0, uint32_t a1, uint32_t a2, uint32_t a3,
                                         uint32_t b0, uint32_t b1) {
    asm volatile(
        "mma.sync.aligned.m16n8k16.row.col.f32.bf16.bf16.f32 "
        "{%0,%1,%2,%3}, {%4,%5,%6,%7}, {%8,%9}, {%0,%1,%2,%3};"
        : "+f"(c0), "+f"(c1), "+f"(c2), "+f"(c3)
        : "r"(a0), "r"(a1), "r"(a2), "r"(a3), "r"(b0), "r"(b1));
}

__device__ __forceinline__ void cp16(uint32_t dst, const void* src) {
    asm volatile("cp.async.cg.shared.global [%0], [%1], 16;"
                 :: "r"(dst), "l"(src) : "memory");
}
#define CP_COMMIT() asm volatile("cp.async.commit_group;" ::: "memory")
#define CP_WAIT1()  asm volatile("cp.async.wait_group 1;" ::: "memory")

// ---------------------------------------------------------------------------
// split kernels: fp32 -> (hi, lo) bf16
// ---------------------------------------------------------------------------
__global__ void __launch_bounds__(256) split_f32_kernel(
    const float* __restrict__ X, __nv_bfloat16* __restrict__ Xh,
    __nv_bfloat16* __restrict__ Xl, int n4)
{
    int i = blockIdx.x * blockDim.x + threadIdx.x;
    if (i >= n4) return;
    float4 v = ((const float4*)X)[i];
    __nv_bfloat16 h0 = __float2bfloat16(v.x), h1 = __float2bfloat16(v.y);
    __nv_bfloat16 h2 = __float2bfloat16(v.z), h3 = __float2bfloat16(v.w);
    __nv_bfloat16 l0 = __float2bfloat16(v.x - __bfloat162float(h0));
    __nv_bfloat16 l1 = __float2bfloat16(v.y - __bfloat162float(h1));
    __nv_bfloat16 l2 = __float2bfloat16(v.z - __bfloat162float(h2));
    __nv_bfloat16 l3 = __float2bfloat16(v.w - __bfloat162float(h3));
    ((__nv_bfloat162*)Xh)[2*i]   = __nv_bfloat162(h0, h1);
    ((__nv_bfloat162*)Xh)[2*i+1] = __nv_bfloat162(h2, h3);
    ((__nv_bfloat162*)Xl)[2*i]   = __nv_bfloat162(l0, l1);
    ((__nv_bfloat162*)Xl)[2*i+1] = __nv_bfloat162(l2, l3);
}

// W[K][N] (row-major, N contiguous) -> Th/Tl [N][K] (K contiguous), split bf16
__global__ void __launch_bounds__(256) split_wT_kernel(
    const float* __restrict__ W, __nv_bfloat16* __restrict__ Th,
    __nv_bfloat16* __restrict__ Tl, int Kdim, int Ndim)
{
    __shared__ float t[32][33];
    int n0 = blockIdx.x * 32, k0 = blockIdx.y * 32;
    int tx = threadIdx.x, ty = threadIdx.y;   // 32 x 8
    #pragma unroll
    for (int i = ty; i < 32; i += 8)
        t[i][tx] = W[(size_t)(k0 + i) * Ndim + n0 + tx];
    __syncthreads();
    #pragma unroll
    for (int i = ty; i < 32; i += 8) {
        float v = t[tx][i];                   // = W[k0+tx][n0+i]
        __nv_bfloat16 h = __float2bfloat16(v);
        __nv_bfloat16 l = __float2bfloat16(v - __bfloat162float(h));
        Th[(size_t)(n0 + i) * Kdim + k0 + tx] = h;
        Tl[(size_t)(n0 + i) * Kdim + k0 + tx] = l;
    }
}

// ---------------------------------------------------------------------------
// Pipelined mma.sync split-bf16 GEMM: C[128,128] = A[128,1024] @ B[128,1024]^T
//   C = Ah@Bh + Ah@Bl + Al@Bh  (fp32 accumulate)
// BK=32, 2-stage cp.async double buffer, 8 warps (4m x 2n), warp tile 32x64.
// mode 0: A = x, B = w_qkvT, epilogue scatters into g_q/g_k/g_v + bias
// mode 1: A = vals, B = w_oT, epilogue writes Cout + bias
// ---------------------------------------------------------------------------
#define GK      1024
#define BKC     32
#define NCHUNK  (GK / BKC)                  // 32
#define PITCH   40                          // elems; 80B rows, LDSM conflict-free
#define TILE_B  (128 * PITCH * 2)           // 10240 bytes
#define STAGE_B (4 * TILE_B)                // 40960 bytes
#define GEMM_SMEM (2 * STAGE_B)             // 81920 bytes

__global__ void __launch_bounds__(256, 2) mma_gemm_kernel(
    const float* __restrict__ bias, float* __restrict__ Cout, int Ntot, int mode)
{
    extern __shared__ char smem[];
    const uint32_t sbase = smem_u32(smem);

    const int tid = threadIdx.x;
    const int wid = tid >> 5, lane = tid & 31;
    const int wm = wid & 3;          // m-group: rows wm*32..wm*32+31
    const int wn = wid >> 2;         // n-group: cols wn*64..wn*64+63
    const int bx = blockIdx.x, by = blockIdx.y;

    const __nv_bfloat16 *Ah, *Al, *Bh, *Bl;
    if (mode == 0) { Ah = g_xh; Al = g_xl; Bh = g_wqkvT_h; Bl = g_wqkvT_l; }
    else           { Ah = g_vh; Al = g_vl; Bh = g_woT_h;   Bl = g_woT_l;   }

    const size_t aBase = (size_t)(by * 128) * GK;
    const size_t bBase = (size_t)(bx * 128) * GK;

    // per-thread cp.async assignment: 512 16B-chunks per tensor per stage,
    // thread does 2 per tensor.
    const int cpr0 = tid >> 2;              // row for i = tid
    const int cpc0 = (tid & 3) * 8;         // elem col (8 bf16 = 16B)
    const int cpr1 = (tid + 256) >> 2;
    const int cpc1 = ((tid + 256) & 3) * 8;

    float acc[2][8][4];
    #pragma unroll
    for (int mf = 0; mf < 2; mf++)
        #pragma unroll
        for (int nf = 0; nf < 8; nf++)
            #pragma unroll
            for (int e = 0; e < 4; e++) acc[mf][nf][e] = 0.f;

    // ldmatrix per-lane address components
    const int l7 = lane & 7;
    const int aRowOff = ((lane >> 3) & 1) * 8 + l7;
    const int aKOff   = (lane >> 4) * 8;
    const int bRowOff = ((lane >> 4) & 1) * 8 + l7;
    const int bKOff   = ((lane >> 3) & 1) * 8;

    // stage loader
    auto load_stage = [&](int stage, int kc) {
        const int kOff = kc * BKC;
        const uint32_t st = sbase + stage * STAGE_B;
        const __nv_bfloat16* srcs[4] = {
            Ah + aBase + kOff, Al + aBase + kOff,
            Bh + bBase + kOff, Bl + bBase + kOff };
        #pragma unroll
        for (int t = 0; t < 4; t++) {
            const uint32_t dst = st + t * TILE_B;
            cp16(dst + (uint32_t)(cpr0 * PITCH + cpc0) * 2,
                 srcs[t] + (size_t)cpr0 * GK + cpc0);
            cp16(dst + (uint32_t)(cpr1 * PITCH + cpc1) * 2,
                 srcs[t] + (size_t)cpr1 * GK + cpc1);
        }
    };

    load_stage(0, 0);
    CP_COMMIT();

    for (int kc = 0; kc < NCHUNK; kc++) {
        if (kc + 1 < NCHUNK) load_stage((kc + 1) & 1, kc + 1);
        CP_COMMIT();
        CP_WAIT1();               // chunk kc's group complete
        __syncthreads();

        const uint32_t st = sbase + (kc & 1) * STAGE_B;
        const uint32_t sA_h = st;
        const uint32_t sA_l = st + TILE_B;
        const uint32_t sB_h = st + 2*TILE_B;
        const uint32_t sB_l = st + 3*TILE_B;

        #pragma unroll
        for (int ks = 0; ks < 2; ks++) {
            const int kcol = ks * 16;
            uint32_t ah[2][4], al[2][4];
            #pragma unroll
            for (int mf = 0; mf < 2; mf++) {
                uint32_t off = (uint32_t)((wm*32 + mf*16 + aRowOff) * PITCH
                                          + kcol + aKOff) * 2;
                ldsm_x4(ah[mf][0], ah[mf][1], ah[mf][2], ah[mf][3], sA_h + off);
                ldsm_x4(al[mf][0], al[mf][1], al[mf][2], al[mf][3], sA_l + off);
            }
            #pragma unroll
            for (int nh = 0; nh < 2; nh++) {
                uint32_t bh[4][2], bl[4][2];
                #pragma unroll
                for (int g = 0; g < 2; g++) {
                    uint32_t off = (uint32_t)((wn*64 + nh*32 + g*16 + bRowOff) * PITCH
                                              + kcol + bKOff) * 2;
                    ldsm_x4(bh[g*2][0], bh[g*2][1], bh[g*2+1][0], bh[g*2+1][1],
                            sB_h + off);
                    ldsm_x4(bl[g*2][0], bl[g*2][1], bl[g*2+1][0], bl[g*2+1][1],
                            sB_l + off);
                }
                #pragma unroll
                for (int mf = 0; mf < 2; mf++)
                    #pragma unroll
                    for (int nn = 0; nn < 4; nn++) {
                        float* c = acc[mf][nh*4 + nn];
                        mma_bf16(c[0], c[1], c[2], c[3],
                                 ah[mf][0], ah[mf][1], ah[mf][2], ah[mf][3],
                                 bh[nn][0], bh[nn][1]);
                        mma_bf16(c[0], c[1], c[2], c[3],
                                 ah[mf][0], ah[mf][1], ah[mf][2], ah[mf][3],
                                 bl[nn][0], bl[nn][1]);
                        mma_bf16(c[0], c[1], c[2], c[3],
                                 al[mf][0], al[mf][1], al[mf][2], al[mf][3],
                                 bh[nn][0], bh[nn][1]);
                    }
            }
        }
        __syncthreads();          // all reads of stage kc&1 done before reuse
    }

    // ---- epilogue ----
    const int g = lane >> 2, cq = lane & 3;
    #pragma unroll
    for (int mf = 0; mf < 2; mf++) {
        #pragma unroll
        for (int nf = 0; nf < 8; nf++) {
            const int n = bx*128 + wn*64 + nf*8 + 2*cq;
            const float b0 = bias[n], b1 = bias[n+1];
            #pragma unroll
            for (int half = 0; half < 2; half++) {
                const int m = by*128 + wm*32 + mf*16 + g + half*8;
                float2 v2;
                v2.x = acc[mf][nf][half*2 + 0] + b0;
                v2.y = acc[mf][nf][half*2 + 1] + b1;
                if (mode == 0) {
                    const int bb = m >> 11, s = m & 2047;
                    const int h = n / 192;
                    const int rr = n - h * 192;
                    const size_t base = (((size_t)bb * H_ + h) * S_ + s) * HD_;
                    if (rr < 64)       *(float2*)&g_q[base + rr]       = v2;
                    else if (rr < 128) *(float2*)&g_k[base + rr - 64]  = v2;
                    else               *(float2*)&g_v[base + rr - 128] = v2;
                } else {
                    *(float2*)&Cout[(size_t)m * Ntot + n] = v2;
                }
            }
        }
    }
}

// ---------------------------------------------------------------------------
// FUSED attention: logits + online softmax + probs + p@V (unchanged)
// ---------------------------------------------------------------------------
__global__ void __launch_bounds__(256) attn_fused_kernel(float* __restrict__ attn)
{
    const int head = blockIdx.y;
    const int qt   = (int)gridDim.x - 1 - (int)blockIdx.x;

    const float* qbase = g_q + (size_t)head*S_*HD_;
    const float* kbase = g_k + (size_t)head*S_*HD_;
    const float* vbase = g_v + (size_t)head*S_*HD_;
    float* out = attn + (size_t)head*S_*S_;

    const int tid = threadIdx.x;
    const int ty = tid >> 4, tx = tid & 15;

    __shared__ float Qs[64][68];
    __shared__ float Ks[64][68];
    __shared__ float msnap[32][64];

    {
        const int c0 = (qt + 1) * 64;
        const int nc = S_ - c0;
        if (nc > 0) {
            const int n4 = nc >> 2;
            const float4 z = make_float4(0.f, 0.f, 0.f, 0.f);
            for (int idx = tid; idx < 64 * n4; idx += 256) {
                int r = idx / n4;
                int c = (idx - r * n4) << 2;
                *(float4*)&out[(size_t)(qt*64 + r)*S_ + c0 + c] = z;
            }
        }
    }

    for (int idx = tid; idx < 64*16; idx += 256) {
        int r = idx >> 4;
        int c = (idx & 15) * 4;
        float4 q4 = *(const float4*)&qbase[(size_t)(qt*64 + r)*HD_ + c];
        Qs[c+0][r] = q4.x; Qs[c+1][r] = q4.y; Qs[c+2][r] = q4.z; Qs[c+3][r] = q4.w;
    }

    float m_run[4], s_run[4];
    #pragma unroll
    for (int i = 0; i < 4; i++) { m_run[i] = -INFINITY; s_run[i] = 0.f; }

    const float scale = 0.125f;

    for (int kt = 0; kt <= qt; kt++) {
        __syncthreads();
        for (int idx = tid; idx < 64*16; idx += 256) {
            int r = idx >> 4;
            int c = (idx & 15) * 4;
            float4 k4 = *(const float4*)&kbase[(size_t)(kt*64 + r)*HD_ + c];
            Ks[c+0][r] = k4.x; Ks[c+1][r] = k4.y; Ks[c+2][r] = k4.z; Ks[c+3][r] = k4.w;
        }
        __syncthreads();

        float acc[4][4];
        #pragma unroll
        for (int i = 0; i < 4; i++)
            #pragma unroll
            for (int j = 0; j < 4; j++) acc[i][j] = 0.f;

        #pragma unroll 4
        for (int k = 0; k < 64; k++) {
            float4 a = *(float4*)&Qs[k][ty*4];
            float4 b = *(float4*)&Ks[k][tx*4];
            acc[0][0] = fmaf(a.x,b.x,acc[0][0]); acc[0][1] = fmaf(a.x,b.y,acc[0][1]);
            acc[0][2] = fmaf(a.x,b.z,acc[0][2]); acc[0][3] = fmaf(a.x,b.w,acc[0][3]);
            acc[1][0] = fmaf(a.y,b.x,acc[1][0]); acc[1][1] = fmaf(a.y,b.y,acc[1][1]);
            acc[1][2] = fmaf(a.y,b.z,acc[1][2]); acc[1][3] = fmaf(a.y,b.w,acc[1][3]);
            acc[2][0] = fmaf(a.z,b.x,acc[2][0]); acc[2][1] = fmaf(a.z,b.y,acc[2][1]);
            acc[2][2] = fmaf(a.z,b.z,acc[2][2]); acc[2][3] = fmaf(a.z,b.w,acc[2][3]);
            acc[3][0] = fmaf(a.w,b.x,acc[3][0]); acc[3][1] = fmaf(a.w,b.y,acc[3][1]);
            acc[3][2] = fmaf(a.w,b.z,acc[3][2]); acc[3][3] = fmaf(a.w,b.w,acc[3][3]);
        }

        const bool diag = (kt == qt);
        #pragma unroll
        for (int i = 0; i < 4; i++) {
            const int row = qt*64 + ty*4 + i;
            float l[4]; bool valid[4];
            #pragma unroll
            for (int j = 0; j < 4; j++) {
                int col = kt*64 + tx*4 + j;
                l[j] = acc[i][j] * scale;
                valid[j] = !diag || (col <= row);
            }
            float t = -INFINITY;
            #pragma unroll
            for (int j = 0; j < 4; j++) t = fmaxf(t, valid[j] ? l[j] : -INFINITY);
            #pragma unroll
            for (int o = 8; o > 0; o >>= 1)
                t = fmaxf(t, __shfl_xor_sync(0xffffffffu, t, o));
            float m_new = fmaxf(m_run[i], t);

            float e[4], rs = 0.f;
            #pragma unroll
            for (int j = 0; j < 4; j++) {
                e[j] = valid[j] ? __expf(l[j] - m_new) : 0.f;
                rs += e[j];
            }
            *(float4*)&out[(size_t)row*S_ + kt*64 + tx*4] =
                make_float4(e[0], e[1], e[2], e[3]);
            #pragma unroll
            for (int o = 8; o > 0; o >>= 1)
                rs += __shfl_xor_sync(0xffffffffu, rs, o);

            s_run[i] = s_run[i] * __expf(m_run[i] - m_new) + rs;
            m_run[i] = m_new;
            if (tx == 0) msnap[kt][ty*4 + i] = m_new;
        }
    }

    float inv_s[4], mf[4];
    #pragma unroll
    for (int i = 0; i < 4; i++) { inv_s[i] = 1.f / s_run[i]; mf[i] = m_run[i]; }

    float vacc[4][4];
    #pragma unroll
    for (int i = 0; i < 4; i++)
        #pragma unroll
        for (int j = 0; j < 4; j++) vacc[i][j] = 0.f;

    for (int kt = 0; kt <= qt; kt++) {
        __syncthreads();
        for (int idx = tid; idx < 64*16; idx += 256) {
            int r = idx >> 4;
            int c = (idx & 15) * 4;
            *(float4*)&Ks[r][c] = *(const float4*)&vbase[(size_t)(kt*64 + r)*HD_ + c];
        }
        #pragma unroll
        for (int i = 0; i < 4; i++) {
            const int row = qt*64 + ty*4 + i;
            float4 e4 = *(float4*)&out[(size_t)row*S_ + kt*64 + tx*4];
            float f = __expf(msnap[kt][ty*4 + i] - mf[i]) * inv_s[i];
            e4.x *= f; e4.y *= f; e4.z *= f; e4.w *= f;
            *(float4*)&out[(size_t)row*S_ + kt*64 + tx*4] = e4;
            *(float4*)&Qs[ty*4 + i][tx*4] = e4;
        }
        __syncthreads();

        #pragma unroll 4
        for (int k = 0; k < 64; k++) {
            float a0 = Qs[ty*4+0][k];
            float a1 = Qs[ty*4+1][k];
            float a2 = Qs[ty*4+2][k];
            float a3 = Qs[ty*4+3][k];
            float4 b = *(float4*)&Ks[k][tx*4];
            vacc[0][0] = fmaf(a0,b.x,vacc[0][0]); vacc[0][1] = fmaf(a0,b.y,vacc[0][1]);
            vacc[0][2] = fmaf(a0,b.z,vacc[0][2]); vacc[0][3] = fmaf(a0,b.w,vacc[0][3]);
            vacc[1][0] = fmaf(a1,b.x,vacc[1][0]); vacc[1][1] = fmaf(a1,b.y,vacc[1][1]);
            vacc[1][2] = fmaf(a1,b.z,vacc[1][2]); vacc[1][3] = fmaf(a1,b.w,vacc[1][3]);
            vacc[2][0] = fmaf(a2,b.x,vacc[2][0]); vacc[2][1] = fmaf(a2,b.y,vacc[2][1]);
            vacc[2][2] = fmaf(a2,b.z,vacc[2][2]); vacc[2][3] = fmaf(a2,b.w,vacc[2][3]);
            vacc[3][0] = fmaf(a3,b.x,vacc[3][0]); vacc[3][1] = fmaf(a3,b.y,vacc[3][1]);
            vacc[3][2] = fmaf(a3,b.z,vacc[3][2]); vacc[3][3] = fmaf(a3,b.w,vacc[3][3]);
        }
    }

    const int bb = head >> 4, h = head & 15;
    #pragma unroll
    for (int i = 0; i < 4; i++) {
        int s = qt*64 + ty*4 + i;
        *(float4*)&g_vals[((size_t)bb*S_ + s)*E_ + h*HD_ + tx*4] =
            make_float4(vacc[i][0], vacc[i][1], vacc[i][2], vacc[i][3]);
    }
}

// ---------------------------------------------------------------------------
extern "C" void kernel_launch(void* const* d_in, const int* in_sizes, int n_in,
                              void* d_out, int out_size)
{
    const float* x     = (const float*)d_in[0];   // [B,S,E]
    const float* w_qkv = (const float*)d_in[1];   // [E,3E]
    const float* b_qkv = (const float*)d_in[2];   // [3E]
    const float* w_o   = (const float*)d_in[3];   // [E,E]
    const float* b_o   = (const float*)d_in[4];   // [E]
    // d_in[5] = causal mask (hardcoded)

    float* o_out    = (float*)d_out;                       // [B,S,E]
    float* attn_out = o_out + (size_t)B_ * S_ * E_;        // [B,H,S,S]

    static bool attr_set = false;
    if (!attr_set) {
        cudaFuncSetAttribute(mma_gemm_kernel,
                             cudaFuncAttributeMaxDynamicSharedMemorySize, GEMM_SMEM);
        attr_set = true;
    }

    __nv_bfloat16 *p_xh, *p_xl, *p_wqh, *p_wql, *p_woh, *p_wol, *p_vh, *p_vl;
    cudaGetSymbolAddress((void**)&p_xh,  g_xh);
    cudaGetSymbolAddress((void**)&p_xl,  g_xl);
    cudaGetSymbolAddress((void**)&p_wqh, g_wqkvT_h);
    cudaGetSymbolAddress((void**)&p_wql, g_wqkvT_l);
    cudaGetSymbolAddress((void**)&p_woh, g_woT_h);
    cudaGetSymbolAddress((void**)&p_wol, g_woT_l);
    cudaGetSymbolAddress((void**)&p_vh,  g_vh);
    cudaGetSymbolAddress((void**)&p_vl,  g_vl);
    float* p_vals;
    cudaGetSymbolAddress((void**)&p_vals, g_vals);

    // 0. split inputs to bf16 hi/lo
    {
        int n4 = (MROWS * E_) / 4;
        split_f32_kernel<<<n4 / 256, 256>>>(x, p_xh, p_xl, n4);
        dim3 g1(N3E/32, E_/32);
        split_wT_kernel<<<g1, dim3(32,8)>>>(w_qkv, p_wqh, p_wql, E_, N3E);
        dim3 g2(E_/32, E_/32);
        split_wT_kernel<<<g2, dim3(32,8)>>>(w_o, p_woh, p_wol, E_, E_);
    }
    // 1. QKV projection (pipelined tensor-core GEMM) + scatter
    {
        dim3 grid(N3E/128, MROWS/128);                 // (24, 64)
        mma_gemm_kernel<<<grid, 256, GEMM_SMEM>>>(b_qkv, nullptr, N3E, 0);
    }
    // 2. fused attention
    {
        dim3 grid(S_/64, BH_);
        attn_fused_kernel<<<grid, 256>>>(attn_out);
    }
    // 3. split vals, output projection (pipelined tensor-core GEMM)
    {
        int n4 = (MROWS * E_) / 4;
        split_f32_kernel<<<n4 / 256, 256>>>(p_vals, p_vh, p_vl, n4);
        dim3 grid(E_/128, MROWS/128);                  // (8, 64)
        mma_gemm_kernel<<<grid, 256, GEMM_SMEM>>>(b_o, o_out, E_, 1);
    }
}

// round 6
// speedup vs baseline: 1.8652x; 1.1665x over previous
#include <cuda_runtime.h>
#include <cuda_bf16.h>
#include <cstdint>
#include <math.h>

// Problem constants
#define B_  4
#define S_  2048
#define E_  1024
#define H_  16
#define HD_ 64
#define BH_ (B_*H_)           // 64
#define N3E (3*E_)            // 3072
#define MROWS (B_*S_)         // 8192

// ---------------- scratch (device globals; allocation-free) ----------------
// q/k/v in split-bf16 [B,H,S,HD]
__device__ __nv_bfloat16 g_qh[(size_t)BH_ * S_ * HD_];
__device__ __nv_bfloat16 g_ql[(size_t)BH_ * S_ * HD_];
__device__ __nv_bfloat16 g_kh[(size_t)BH_ * S_ * HD_];
__device__ __nv_bfloat16 g_kl[(size_t)BH_ * S_ * HD_];
__device__ __nv_bfloat16 g_vh[(size_t)BH_ * S_ * HD_];
__device__ __nv_bfloat16 g_vl[(size_t)BH_ * S_ * HD_];
// attention output in split-bf16 [B,S,E]
__device__ __nv_bfloat16 g_oh[(size_t)MROWS * E_];
__device__ __nv_bfloat16 g_ol[(size_t)MROWS * E_];
// x and weights in split-bf16
__device__ __nv_bfloat16 g_xh[(size_t)MROWS * E_];
__device__ __nv_bfloat16 g_xl[(size_t)MROWS * E_];
__device__ __nv_bfloat16 g_wqkvT_h[(size_t)N3E * E_];   // [N=3072][K=1024]
__device__ __nv_bfloat16 g_wqkvT_l[(size_t)N3E * E_];
__device__ __nv_bfloat16 g_woT_h[(size_t)E_ * E_];      // [N=1024][K=1024]
__device__ __nv_bfloat16 g_woT_l[(size_t)E_ * E_];

// ---------------- helpers ----------------
__device__ __forceinline__ uint32_t smem_u32(const void* p) {
    uint32_t a;
    asm("{ .reg .u64 t; cvta.to.shared.u64 t, %1; cvt.u32.u64 %0, t; }"
        : "=r"(a) : "l"(p));
    return a;
}
__device__ __forceinline__ void ldsm_x4(uint32_t& r0, uint32_t& r1,
                                        uint32_t& r2, uint32_t& r3, uint32_t addr) {
    asm volatile("ldmatrix.sync.aligned.m8n8.x4.shared.b16 {%0,%1,%2,%3}, [%4];"
                 : "=r"(r0), "=r"(r1), "=r"(r2), "=r"(r3) : "r"(addr));
}
__device__ __forceinline__ void ldsm_x4_t(uint32_t& r0, uint32_t& r1,
                                          uint32_t& r2, uint32_t& r3, uint32_t addr) {
    asm volatile("ldmatrix.sync.aligned.m8n8.x4.trans.shared.b16 {%0,%1,%2,%3}, [%4];"
                 : "=r"(r0), "=r"(r1), "=r"(r2), "=r"(r3) : "r"(addr));
}
__device__ __forceinline__ void mma_bf16(float& c0, float& c1, float& c2, float& c3,
                                         uint32_t a0, uint32_t a1, uint32_t a2, uint32_t a3,
                                         uint32_t b0, uint32_t b1) {
    asm volatile(
        "mma.sync.aligned.m16n8k16.row.col.f32.bf16.bf16.f32 "
        "{%0,%1,%2,%3}, {%4,%5,%6,%7}, {%8,%9}, {%0,%1,%2,%3};"
        : "+f"(c0), "+f"(c1), "+f"(c2), "+f"(c3)
        : "r"(a0), "r"(a1), "r"(a2), "r"(a3), "r"(b0), "r"(b1));
}
__device__ __forceinline__ void cp16(uint32_t dst, const void* src) {
    asm volatile("cp.async.cg.shared.global [%0], [%1], 16;"
                 :: "r"(dst), "l"(src) : "memory");
}
#define CP_COMMIT() asm volatile("cp.async.commit_group;" ::: "memory")
#define CP_WAIT1()  asm volatile("cp.async.wait_group 1;" ::: "memory")

__device__ __forceinline__ uint32_t pack_bf16x2(float a, float b) {
    __nv_bfloat162 t = __floats2bfloat162_rn(a, b);
    return *(uint32_t*)&t;
}

// ---------------------------------------------------------------------------
// split kernels
// ---------------------------------------------------------------------------
__global__ void __launch_bounds__(256) split_f32_kernel(
    const float* __restrict__ X, __nv_bfloat16* __restrict__ Xh,
    __nv_bfloat16* __restrict__ Xl, int n4)
{
    int i = blockIdx.x * blockDim.x + threadIdx.x;
    if (i >= n4) return;
    float4 v = ((const float4*)X)[i];
    __nv_bfloat16 h0 = __float2bfloat16(v.x), h1 = __float2bfloat16(v.y);
    __nv_bfloat16 h2 = __float2bfloat16(v.z), h3 = __float2bfloat16(v.w);
    __nv_bfloat16 l0 = __float2bfloat16(v.x - __bfloat162float(h0));
    __nv_bfloat16 l1 = __float2bfloat16(v.y - __bfloat162float(h1));
    __nv_bfloat16 l2 = __float2bfloat16(v.z - __bfloat162float(h2));
    __nv_bfloat16 l3 = __float2bfloat16(v.w - __bfloat162float(h3));
    ((__nv_bfloat162*)Xh)[2*i]   = __nv_bfloat162(h0, h1);
    ((__nv_bfloat162*)Xh)[2*i+1] = __nv_bfloat162(h2, h3);
    ((__nv_bfloat162*)Xl)[2*i]   = __nv_bfloat162(l0, l1);
    ((__nv_bfloat162*)Xl)[2*i+1] = __nv_bfloat162(l2, l3);
}

__global__ void __launch_bounds__(256) split_wT_kernel(
    const float* __restrict__ W, __nv_bfloat16* __restrict__ Th,
    __nv_bfloat16* __restrict__ Tl, int Kdim, int Ndim)
{
    __shared__ float t[32][33];
    int n0 = blockIdx.x * 32, k0 = blockIdx.y * 32;
    int tx = threadIdx.x, ty = threadIdx.y;
    #pragma unroll
    for (int i = ty; i < 32; i += 8)
        t[i][tx] = W[(size_t)(k0 + i) * Ndim + n0 + tx];
    __syncthreads();
    #pragma unroll
    for (int i = ty; i < 32; i += 8) {
        float v = t[tx][i];
        __nv_bfloat16 h = __float2bfloat16(v);
        __nv_bfloat16 l = __float2bfloat16(v - __bfloat162float(h));
        Th[(size_t)(n0 + i) * Kdim + k0 + tx] = h;
        Tl[(size_t)(n0 + i) * Kdim + k0 + tx] = l;
    }
}

// ---------------------------------------------------------------------------
// Pipelined mma.sync split-bf16 GEMM (from R5).
// mode 0: A = x, B = w_qkvT, epilogue scatters split-bf16 q/k/v + bias
// mode 1: A = attn-out (g_oh/g_ol), B = w_oT, epilogue writes f32 Cout + bias
// ---------------------------------------------------------------------------
#define GK      1024
#define BKC     32
#define NCHUNK  (GK / BKC)
#define PITCH   40
#define TILE_B  (128 * PITCH * 2)
#define STAGE_B (4 * TILE_B)
#define GEMM_SMEM (2 * STAGE_B)

__global__ void __launch_bounds__(256, 2) mma_gemm_kernel(
    const float* __restrict__ bias, float* __restrict__ Cout, int Ntot, int mode)
{
    extern __shared__ char smem[];
    const uint32_t sbase = smem_u32(smem);

    const int tid = threadIdx.x;
    const int wid = tid >> 5, lane = tid & 31;
    const int wm = wid & 3;
    const int wn = wid >> 2;
    const int bx = blockIdx.x, by = blockIdx.y;

    const __nv_bfloat16 *Ah, *Al, *Bh, *Bl;
    if (mode == 0) { Ah = g_xh; Al = g_xl; Bh = g_wqkvT_h; Bl = g_wqkvT_l; }
    else           { Ah = g_oh; Al = g_ol; Bh = g_woT_h;   Bl = g_woT_l;   }

    const size_t aBase = (size_t)(by * 128) * GK;
    const size_t bBase = (size_t)(bx * 128) * GK;

    const int cpr0 = tid >> 2;
    const int cpc0 = (tid & 3) * 8;
    const int cpr1 = (tid + 256) >> 2;
    const int cpc1 = ((tid + 256) & 3) * 8;

    float acc[2][8][4];
    #pragma unroll
    for (int mf = 0; mf < 2; mf++)
        #pragma unroll
        for (int nf = 0; nf < 8; nf++)
            #pragma unroll
            for (int e = 0; e < 4; e++) acc[mf][nf][e] = 0.f;

    const int l7 = lane & 7;
    const int aRowOff = ((lane >> 3) & 1) * 8 + l7;
    const int aKOff   = (lane >> 4) * 8;
    const int bRowOff = ((lane >> 4) & 1) * 8 + l7;
    const int bKOff   = ((lane >> 3) & 1) * 8;

    auto load_stage = [&](int stage, int kc) {
        const int kOff = kc * BKC;
        const uint32_t st = sbase + stage * STAGE_B;
        const __nv_bfloat16* srcs[4] = {
            Ah + aBase + kOff, Al + aBase + kOff,
            Bh + bBase + kOff, Bl + bBase + kOff };
        #pragma unroll
        for (int t = 0; t < 4; t++) {
            const uint32_t dst = st + t * TILE_B;
            cp16(dst + (uint32_t)(cpr0 * PITCH + cpc0) * 2,
                 srcs[t] + (size_t)cpr0 * GK + cpc0);
            cp16(dst + (uint32_t)(cpr1 * PITCH + cpc1) * 2,
                 srcs[t] + (size_t)cpr1 * GK + cpc1);
        }
    };

    load_stage(0, 0);
    CP_COMMIT();

    for (int kc = 0; kc < NCHUNK; kc++) {
        if (kc + 1 < NCHUNK) load_stage((kc + 1) & 1, kc + 1);
        CP_COMMIT();
        CP_WAIT1();
        __syncthreads();

        const uint32_t st = sbase + (kc & 1) * STAGE_B;
        const uint32_t sA_h = st;
        const uint32_t sA_l = st + TILE_B;
        const uint32_t sB_h = st + 2*TILE_B;
        const uint32_t sB_l = st + 3*TILE_B;

        #pragma unroll
        for (int ks = 0; ks < 2; ks++) {
            const int kcol = ks * 16;
            uint32_t ah[2][4], al[2][4];
            #pragma unroll
            for (int mf = 0; mf < 2; mf++) {
                uint32_t off = (uint32_t)((wm*32 + mf*16 + aRowOff) * PITCH
                                          + kcol + aKOff) * 2;
                ldsm_x4(ah[mf][0], ah[mf][1], ah[mf][2], ah[mf][3], sA_h + off);
                ldsm_x4(al[mf][0], al[mf][1], al[mf][2], al[mf][3], sA_l + off);
            }
            #pragma unroll
            for (int nh = 0; nh < 2; nh++) {
                uint32_t bh[4][2], bl[4][2];
                #pragma unroll
                for (int g = 0; g < 2; g++) {
                    uint32_t off = (uint32_t)((wn*64 + nh*32 + g*16 + bRowOff) * PITCH
                                              + kcol + bKOff) * 2;
                    ldsm_x4(bh[g*2][0], bh[g*2][1], bh[g*2+1][0], bh[g*2+1][1],
                            sB_h + off);
                    ldsm_x4(bl[g*2][0], bl[g*2][1], bl[g*2+1][0], bl[g*2+1][1],
                            sB_l + off);
                }
                #pragma unroll
                for (int mf = 0; mf < 2; mf++)
                    #pragma unroll
                    for (int nn = 0; nn < 4; nn++) {
                        float* c = acc[mf][nh*4 + nn];
                        mma_bf16(c[0], c[1], c[2], c[3],
                                 ah[mf][0], ah[mf][1], ah[mf][2], ah[mf][3],
                                 bh[nn][0], bh[nn][1]);
                        mma_bf16(c[0], c[1], c[2], c[3],
                                 ah[mf][0], ah[mf][1], ah[mf][2], ah[mf][3],
                                 bl[nn][0], bl[nn][1]);
                        mma_bf16(c[0], c[1], c[2], c[3],
                                 al[mf][0], al[mf][1], al[mf][2], al[mf][3],
                                 bh[nn][0], bh[nn][1]);
                    }
            }
        }
        __syncthreads();
    }

    const int g = lane >> 2, cq = lane & 3;
    #pragma unroll
    for (int mf = 0; mf < 2; mf++) {
        #pragma unroll
        for (int nf = 0; nf < 8; nf++) {
            const int n = bx*128 + wn*64 + nf*8 + 2*cq;
            const float b0 = bias[n], b1 = bias[n+1];
            #pragma unroll
            for (int half = 0; half < 2; half++) {
                const int m = by*128 + wm*32 + mf*16 + g + half*8;
                float vx = acc[mf][nf][half*2 + 0] + b0;
                float vy = acc[mf][nf][half*2 + 1] + b1;
                if (mode == 0) {
                    // split to bf16 hi/lo and scatter into q/k/v
                    __nv_bfloat16 hx = __float2bfloat16(vx);
                    __nv_bfloat16 hy = __float2bfloat16(vy);
                    __nv_bfloat16 lx = __float2bfloat16(vx - __bfloat162float(hx));
                    __nv_bfloat16 ly = __float2bfloat16(vy - __bfloat162float(hy));
                    __nv_bfloat162 h2(hx, hy), l2(lx, ly);
                    const int bb = m >> 11, s = m & 2047;
                    const int h = n / 192;
                    const int rr = n - h * 192;
                    const size_t base = (((size_t)bb * H_ + h) * S_ + s) * HD_;
                    if (rr < 64) {
                        *(__nv_bfloat162*)&g_qh[base + rr] = h2;
                        *(__nv_bfloat162*)&g_ql[base + rr] = l2;
                    } else if (rr < 128) {
                        *(__nv_bfloat162*)&g_kh[base + rr - 64] = h2;
                        *(__nv_bfloat162*)&g_kl[base + rr - 64] = l2;
                    } else {
                        *(__nv_bfloat162*)&g_vh[base + rr - 128] = h2;
                        *(__nv_bfloat162*)&g_vl[base + rr - 128] = l2;
                    }
                } else {
                    float2 v2 = make_float2(vx, vy);
                    *(float2*)&Cout[(size_t)m * Ntot + n] = v2;
                }
            }
        }
    }
}

// ---------------------------------------------------------------------------
// Tensor-core flash attention with prob output.
// Per (head, 64-row qtile), 128 threads = 4 warps, warp = 16 rows.
// Pass 1: QK (split-bf16 mma) -> online row max/sum (no gmem writes).
// Pass 2: recompute QK -> p = exp(l - mf)/s, write p once, P@V via mma.
// ---------------------------------------------------------------------------
#define AP 72   // smem pitch (elems); 144B rows, conflict-free LDSM

__global__ void __launch_bounds__(128) attn_tc_kernel(float* __restrict__ attn)
{
    const int head = blockIdx.y;
    const int qt   = (int)gridDim.x - 1 - (int)blockIdx.x;

    const __nv_bfloat16* qh = g_qh + (size_t)head * S_ * HD_;
    const __nv_bfloat16* ql = g_ql + (size_t)head * S_ * HD_;
    const __nv_bfloat16* kh = g_kh + (size_t)head * S_ * HD_;
    const __nv_bfloat16* kl = g_kl + (size_t)head * S_ * HD_;
    const __nv_bfloat16* vh = g_vh + (size_t)head * S_ * HD_;
    const __nv_bfloat16* vl = g_vl + (size_t)head * S_ * HD_;
    float* out = attn + (size_t)head * S_ * S_;

    const int tid = threadIdx.x;
    const int w = tid >> 5, lane = tid & 31;
    const int g = lane >> 2, cq = lane & 3;

    __shared__ __nv_bfloat16 sKh[64 * AP];
    __shared__ __nv_bfloat16 sKl[64 * AP];
    __shared__ __nv_bfloat16 sVh[64 * AP];
    __shared__ __nv_bfloat16 sVl[64 * AP];
    const uint32_t aKh = smem_u32(sKh);
    const uint32_t aKl = smem_u32(sKl);
    const uint32_t aVh = smem_u32(sVh);
    const uint32_t aVl = smem_u32(sVl);

    // ---- zero-fill masked region ----
    {
        const int c0 = (qt + 1) * 64;
        const int nc = S_ - c0;
        if (nc > 0) {
            const int n4 = nc >> 2;
            const float4 z = make_float4(0.f, 0.f, 0.f, 0.f);
            for (int idx = tid; idx < 64 * n4; idx += 128) {
                int r = idx / n4;
                int c = (idx - r * n4) << 2;
                *(float4*)&out[(size_t)(qt*64 + r)*S_ + c0 + c] = z;
            }
        }
    }

    // tile loader: 64 rows x 64 bf16 -> smem pitch AP
    auto load_tile = [&](uint32_t dst, const __nv_bfloat16* src) {
        for (int i = tid; i < 512; i += 128) {
            int r = i >> 3;
            int c = (i & 7) * 8;
            int4 v = *(const int4*)(src + (size_t)r * HD_ + c);
            asm volatile("st.shared.v4.b32 [%0], {%1,%2,%3,%4};" ::
                "r"(dst + (uint32_t)(r * AP + c) * 2),
                "r"(v.x), "r"(v.y), "r"(v.z), "r"(v.w) : "memory");
        }
    };

    const int l7 = lane & 7;
    const int aRowOff = ((lane >> 3) & 1) * 8 + l7;
    const int aKOff   = (lane >> 4) * 8;
    const int bRowOff = ((lane >> 4) & 1) * 8 + l7;
    const int bKOff   = ((lane >> 3) & 1) * 8;
    const int tRow    = lane & 15;            // trans ldsm row
    const int tCol    = (lane >> 4) * 8;      // trans ldsm col

    // ---- stage Q, load A-fragments into registers ----
    load_tile(aKh, qh + (size_t)(qt*64) * HD_);
    load_tile(aKl, ql + (size_t)(qt*64) * HD_);
    __syncthreads();
    uint32_t qfh[4][4], qfl[4][4];
    #pragma unroll
    for (int ks = 0; ks < 4; ks++) {
        uint32_t off = (uint32_t)((w*16 + aRowOff) * AP + ks*16 + aKOff) * 2;
        ldsm_x4(qfh[ks][0], qfh[ks][1], qfh[ks][2], qfh[ks][3], aKh + off);
        ldsm_x4(qfl[ks][0], qfl[ks][1], qfl[ks][2], qfl[ks][3], aKl + off);
    }
    __syncthreads();

    const int row0 = qt*64 + w*16 + g;
    const int row1 = row0 + 8;
    const float scale = 0.125f;

    // QK into C with scale+mask applied
    float C[8][4];
    auto compute_qk = [&](int kt) {
        #pragma unroll
        for (int f = 0; f < 8; f++)
            #pragma unroll
            for (int e = 0; e < 4; e++) C[f][e] = 0.f;
        #pragma unroll
        for (int ks = 0; ks < 4; ks++) {
            #pragma unroll
            for (int nb = 0; nb < 4; nb++) {
                uint32_t off = (uint32_t)((nb*16 + bRowOff) * AP + ks*16 + bKOff) * 2;
                uint32_t bh0, bh1, bh2, bh3, bl0, bl1, bl2, bl3;
                ldsm_x4(bh0, bh1, bh2, bh3, aKh + off);
                ldsm_x4(bl0, bl1, bl2, bl3, aKl + off);
                float* c0 = C[2*nb];
                float* c1 = C[2*nb + 1];
                mma_bf16(c0[0], c0[1], c0[2], c0[3],
                         qfh[ks][0], qfh[ks][1], qfh[ks][2], qfh[ks][3], bh0, bh1);
                mma_bf16(c0[0], c0[1], c0[2], c0[3],
                         qfh[ks][0], qfh[ks][1], qfh[ks][2], qfh[ks][3], bl0, bl1);
                mma_bf16(c0[0], c0[1], c0[2], c0[3],
                         qfl[ks][0], qfl[ks][1], qfl[ks][2], qfl[ks][3], bh0, bh1);
                mma_bf16(c1[0], c1[1], c1[2], c1[3],
                         qfh[ks][0], qfh[ks][1], qfh[ks][2], qfh[ks][3], bh2, bh3);
                mma_bf16(c1[0], c1[1], c1[2], c1[3],
                         qfh[ks][0], qfh[ks][1], qfh[ks][2], qfh[ks][3], bl2, bl3);
                mma_bf16(c1[0], c1[1], c1[2], c1[3],
                         qfl[ks][0], qfl[ks][1], qfl[ks][2], qfl[ks][3], bh2, bh3);
            }
        }
        // scale + causal mask (only diagonal tile has masked cols)
        const bool diag = (kt == qt);
        #pragma unroll
        for (int f = 0; f < 8; f++) {
            const int cb = kt*64 + f*8 + 2*cq;
            C[f][0] = (diag && cb     > row0) ? -1e30f : C[f][0] * scale;
            C[f][1] = (diag && cb + 1 > row0) ? -1e30f : C[f][1] * scale;
            C[f][2] = (diag && cb     > row1) ? -1e30f : C[f][2] * scale;
            C[f][3] = (diag && cb + 1 > row1) ? -1e30f : C[f][3] * scale;
        }
    };

    // =================== PASS 1: stats only ===================
    float mrun0 = -INFINITY, mrun1 = -INFINITY, srun0 = 0.f, srun1 = 0.f;
    for (int kt = 0; kt <= qt; kt++) {
        load_tile(aKh, kh + (size_t)(kt*64) * HD_);
        load_tile(aKl, kl + (size_t)(kt*64) * HD_);
        __syncthreads();
        compute_qk(kt);

        float t0 = -INFINITY, t1 = -INFINITY;
        #pragma unroll
        for (int f = 0; f < 8; f++) {
            t0 = fmaxf(t0, fmaxf(C[f][0], C[f][1]));
            t1 = fmaxf(t1, fmaxf(C[f][2], C[f][3]));
        }
        #pragma unroll
        for (int o = 1; o <= 2; o <<= 1) {
            t0 = fmaxf(t0, __shfl_xor_sync(0xffffffffu, t0, o));
            t1 = fmaxf(t1, __shfl_xor_sync(0xffffffffu, t1, o));
        }
        const float m0 = fmaxf(mrun0, t0), m1 = fmaxf(mrun1, t1);
        float r0 = 0.f, r1 = 0.f;
        #pragma unroll
        for (int f = 0; f < 8; f++) {
            r0 += __expf(C[f][0] - m0) + __expf(C[f][1] - m0);
            r1 += __expf(C[f][2] - m1) + __expf(C[f][3] - m1);
        }
        #pragma unroll
        for (int o = 1; o <= 2; o <<= 1) {
            r0 += __shfl_xor_sync(0xffffffffu, r0, o);
            r1 += __shfl_xor_sync(0xffffffffu, r1, o);
        }
        srun0 = srun0 * __expf(mrun0 - m0) + r0;  mrun0 = m0;
        srun1 = srun1 * __expf(mrun1 - m1) + r1;  mrun1 = m1;
        __syncthreads();
    }

    const float mf0 = mrun0, mf1 = mrun1;
    const float inv0 = 1.f / srun0, inv1 = 1.f / srun1;

    // =================== PASS 2: probs + AV ===================
    float O[8][4];
    #pragma unroll
    for (int f = 0; f < 8; f++)
        #pragma unroll
        for (int e = 0; e < 4; e++) O[f][e] = 0.f;

    for (int kt = 0; kt <= qt; kt++) {
        load_tile(aKh, kh + (size_t)(kt*64) * HD_);
        load_tile(aKl, kl + (size_t)(kt*64) * HD_);
        load_tile(aVh, vh + (size_t)(kt*64) * HD_);
        load_tile(aVl, vl + (size_t)(kt*64) * HD_);
        __syncthreads();
        compute_qk(kt);

        // final probs + write
        #pragma unroll
        for (int f = 0; f < 8; f++) {
            C[f][0] = __expf(C[f][0] - mf0) * inv0;
            C[f][1] = __expf(C[f][1] - mf0) * inv0;
            C[f][2] = __expf(C[f][2] - mf1) * inv1;
            C[f][3] = __expf(C[f][3] - mf1) * inv1;
            const int cb = kt*64 + f*8 + 2*cq;
            *(float2*)&out[(size_t)row0 * S_ + cb] = make_float2(C[f][0], C[f][1]);
            *(float2*)&out[(size_t)row1 * S_ + cb] = make_float2(C[f][2], C[f][3]);
        }

        // P@V: k = kt cols (4 x k16), n = HD (8 n8 frags)
        #pragma unroll
        for (int ks2 = 0; ks2 < 4; ks2++) {
            // split P fragment to bf16 hi/lo
            float p00 = C[2*ks2][0],   p01 = C[2*ks2][1];
            float p02 = C[2*ks2][2],   p03 = C[2*ks2][3];
            float p10 = C[2*ks2+1][0], p11 = C[2*ks2+1][1];
            float p12 = C[2*ks2+1][2], p13 = C[2*ks2+1][3];
            uint32_t ah0 = pack_bf16x2(p00, p01);
            uint32_t ah1 = pack_bf16x2(p02, p03);
            uint32_t ah2 = pack_bf16x2(p10, p11);
            uint32_t ah3 = pack_bf16x2(p12, p13);
            // lo residuals
            __nv_bfloat162 h;
            h = *(__nv_bfloat162*)&ah0;
            uint32_t al0 = pack_bf16x2(p00 - __bfloat162float(h.x),
                                       p01 - __bfloat162float(h.y));
            h = *(__nv_bfloat162*)&ah1;
            uint32_t al1 = pack_bf16x2(p02 - __bfloat162float(h.x),
                                       p03 - __bfloat162float(h.y));
            h = *(__nv_bfloat162*)&ah2;
            uint32_t al2 = pack_bf16x2(p10 - __bfloat162float(h.x),
                                       p11 - __bfloat162float(h.y));
            h = *(__nv_bfloat162*)&ah3;
            uint32_t al3 = pack_bf16x2(p12 - __bfloat162float(h.x),
                                       p13 - __bfloat162float(h.y));

            #pragma unroll
            for (int dblk = 0; dblk < 4; dblk++) {
                uint32_t off = (uint32_t)((ks2*16 + tRow) * AP + dblk*16 + tCol) * 2;
                uint32_t vh0, vh1, vh2, vh3, vl0, vl1, vl2, vl3;
                ldsm_x4_t(vh0, vh1, vh2, vh3, aVh + off);
                ldsm_x4_t(vl0, vl1, vl2, vl3, aVl + off);
                float* o0 = O[2*dblk];
                float* o1 = O[2*dblk + 1];
                mma_bf16(o0[0], o0[1], o0[2], o0[3], ah0, ah1, ah2, ah3, vh0, vh1);
                mma_bf16(o0[0], o0[1], o0[2], o0[3], al0, al1, al2, al3, vh0, vh1);
                mma_bf16(o0[0], o0[1], o0[2], o0[3], ah0, ah1, ah2, ah3, vl0, vl1);
                mma_bf16(o1[0], o1[1], o1[2], o1[3], ah0, ah1, ah2, ah3, vh2, vh3);
                mma_bf16(o1[0], o1[1], o1[2], o1[3], al0, al1, al2, al3, vh2, vh3);
                mma_bf16(o1[0], o1[1], o1[2], o1[3], ah0, ah1, ah2, ah3, vl2, vl3);
            }
        }
        __syncthreads();
    }

    // ---- epilogue: write O as split bf16 to g_oh/g_ol [B,S,E] ----
    const int bb = head >> 4, hh = head & 15;
    #pragma unroll
    for (int f = 0; f < 8; f++) {
        const int e = hh * HD_ + f*8 + 2*cq;
        #pragma unroll
        for (int half = 0; half < 2; half++) {
            const int s = (half == 0) ? row0 : row1;
            float vx = O[f][half*2 + 0], vy = O[f][half*2 + 1];
            __nv_bfloat16 hx = __float2bfloat16(vx);
            __nv_bfloat16 hy = __float2bfloat16(vy);
            __nv_bfloat16 lx = __float2bfloat16(vx - __bfloat162float(hx));
            __nv_bfloat16 ly = __float2bfloat16(vy - __bfloat162float(hy));
            const size_t idx = ((size_t)bb * S_ + s) * E_ + e;
            *(__nv_bfloat162*)&g_oh[idx] = __nv_bfloat162(hx, hy);
            *(__nv_bfloat162*)&g_ol[idx] = __nv_bfloat162(lx, ly);
        }
    }
}

// ---------------------------------------------------------------------------
extern "C" void kernel_launch(void* const* d_in, const int* in_sizes, int n_in,
                              void* d_out, int out_size)
{
    const float* x     = (const float*)d_in[0];   // [B,S,E]
    const float* w_qkv = (const float*)d_in[1];   // [E,3E]
    const float* b_qkv = (const float*)d_in[2];   // [3E]
    const float* w_o   = (const float*)d_in[3];   // [E,E]
    const float* b_o   = (const float*)d_in[4];   // [E]
    // d_in[5] = causal mask (hardcoded)

    float* o_out    = (float*)d_out;                       // [B,S,E]
    float* attn_out = o_out + (size_t)B_ * S_ * E_;        // [B,H,S,S]

    static bool attr_set = false;
    if (!attr_set) {
        cudaFuncSetAttribute(mma_gemm_kernel,
                             cudaFuncAttributeMaxDynamicSharedMemorySize, GEMM_SMEM);
        attr_set = true;
    }

    __nv_bfloat16 *p_xh, *p_xl, *p_wqh, *p_wql, *p_woh, *p_wol;
    cudaGetSymbolAddress((void**)&p_xh,  g_xh);
    cudaGetSymbolAddress((void**)&p_xl,  g_xl);
    cudaGetSymbolAddress((void**)&p_wqh, g_wqkvT_h);
    cudaGetSymbolAddress((void**)&p_wql, g_wqkvT_l);
    cudaGetSymbolAddress((void**)&p_woh, g_woT_h);
    cudaGetSymbolAddress((void**)&p_wol, g_woT_l);

    // 0. split inputs to bf16 hi/lo
    {
        int n4 = (MROWS * E_) / 4;
        split_f32_kernel<<<n4 / 256, 256>>>(x, p_xh, p_xl, n4);
        dim3 g1(N3E/32, E_/32);
        split_wT_kernel<<<g1, dim3(32,8)>>>(w_qkv, p_wqh, p_wql, E_, N3E);
        dim3 g2(E_/32, E_/32);
        split_wT_kernel<<<g2, dim3(32,8)>>>(w_o, p_woh, p_wol, E_, E_);
    }
    // 1. QKV projection (pipelined tensor-core GEMM) -> split-bf16 q/k/v
    {
        dim3 grid(N3E/128, MROWS/128);
        mma_gemm_kernel<<<grid, 256, GEMM_SMEM>>>(b_qkv, nullptr, N3E, 0);
    }
    // 2. tensor-core flash attention (writes probs + split-bf16 O)
    {
        dim3 grid(S_/64, BH_);
        attn_tc_kernel<<<grid, 128>>>(attn_out);
    }
    // 3. output projection (pipelined tensor-core GEMM)
    {
        dim3 grid(E_/128, MROWS/128);
        mma_gemm_kernel<<<grid, 256, GEMM_SMEM>>>(b_o, o_out, E_, 1);
    }
}

// round 7
// speedup vs baseline: 2.5211x; 1.3517x over previous
#include <cuda_runtime.h>
#include <cuda_bf16.h>
#include <cstdint>
#include <math.h>

// Problem constants
#define B_  4
#define S_  2048
#define E_  1024
#define H_  16
#define HD_ 64
#define BH_ (B_*H_)           // 64
#define N3E (3*E_)            // 3072
#define MROWS (B_*S_)         // 8192

// ---------------- scratch (device globals; allocation-free) ----------------
__device__ __nv_bfloat16 g_qh[(size_t)BH_ * S_ * HD_];
__device__ __nv_bfloat16 g_ql[(size_t)BH_ * S_ * HD_];
__device__ __nv_bfloat16 g_kh[(size_t)BH_ * S_ * HD_];
__device__ __nv_bfloat16 g_kl[(size_t)BH_ * S_ * HD_];
__device__ __nv_bfloat16 g_vh[(size_t)BH_ * S_ * HD_];
__device__ __nv_bfloat16 g_vl[(size_t)BH_ * S_ * HD_];
__device__ __nv_bfloat16 g_oh[(size_t)MROWS * E_];
__device__ __nv_bfloat16 g_ol[(size_t)MROWS * E_];
__device__ __nv_bfloat16 g_xh[(size_t)MROWS * E_];
__device__ __nv_bfloat16 g_xl[(size_t)MROWS * E_];
__device__ __nv_bfloat16 g_wqkvT_h[(size_t)N3E * E_];
__device__ __nv_bfloat16 g_wqkvT_l[(size_t)N3E * E_];
__device__ __nv_bfloat16 g_woT_h[(size_t)E_ * E_];
__device__ __nv_bfloat16 g_woT_l[(size_t)E_ * E_];

// ---------------- helpers ----------------
__device__ __forceinline__ uint32_t smem_u32(const void* p) {
    uint32_t a;
    asm("{ .reg .u64 t; cvta.to.shared.u64 t, %1; cvt.u32.u64 %0, t; }"
        : "=r"(a) : "l"(p));
    return a;
}
__device__ __forceinline__ void ldsm_x4(uint32_t& r0, uint32_t& r1,
                                        uint32_t& r2, uint32_t& r3, uint32_t addr) {
    asm volatile("ldmatrix.sync.aligned.m8n8.x4.shared.b16 {%0,%1,%2,%3}, [%4];"
                 : "=r"(r0), "=r"(r1), "=r"(r2), "=r"(r3) : "r"(addr));
}
__device__ __forceinline__ void ldsm_x4_t(uint32_t& r0, uint32_t& r1,
                                          uint32_t& r2, uint32_t& r3, uint32_t addr) {
    asm volatile("ldmatrix.sync.aligned.m8n8.x4.trans.shared.b16 {%0,%1,%2,%3}, [%4];"
                 : "=r"(r0), "=r"(r1), "=r"(r2), "=r"(r3) : "r"(addr));
}
__device__ __forceinline__ void mma_bf16(float& c0, float& c1, float& c2, float& c3,
                                         uint32_t a0, uint32_t a1, uint32_t a2, uint32_t a3,
                                         uint32_t b0, uint32_t b1) {
    asm volatile(
        "mma.sync.aligned.m16n8k16.row.col.f32.bf16.bf16.f32 "
        "{%0,%1,%2,%3}, {%4,%5,%6,%7}, {%8,%9}, {%0,%1,%2,%3};"
        : "+f"(c0), "+f"(c1), "+f"(c2), "+f"(c3)
        : "r"(a0), "r"(a1), "r"(a2), "r"(a3), "r"(b0), "r"(b1));
}
__device__ __forceinline__ void cp16(uint32_t dst, const void* src) {
    asm volatile("cp.async.cg.shared.global [%0], [%1], 16;"
                 :: "r"(dst), "l"(src) : "memory");
}
#define CP_COMMIT() asm volatile("cp.async.commit_group;" ::: "memory")
#define CP_WAIT1()  asm volatile("cp.async.wait_group 1;" ::: "memory")
#define CP_WAIT0()  asm volatile("cp.async.wait_group 0;" ::: "memory")

__device__ __forceinline__ uint32_t pack_bf16x2(float a, float b) {
    __nv_bfloat162 t = __floats2bfloat162_rn(a, b);
    return *(uint32_t*)&t;
}

// ---------------------------------------------------------------------------
// split kernels
// ---------------------------------------------------------------------------
__global__ void __launch_bounds__(256) split_f32_kernel(
    const float* __restrict__ X, __nv_bfloat16* __restrict__ Xh,
    __nv_bfloat16* __restrict__ Xl, int n4)
{
    int i = blockIdx.x * blockDim.x + threadIdx.x;
    if (i >= n4) return;
    float4 v = ((const float4*)X)[i];
    __nv_bfloat16 h0 = __float2bfloat16(v.x), h1 = __float2bfloat16(v.y);
    __nv_bfloat16 h2 = __float2bfloat16(v.z), h3 = __float2bfloat16(v.w);
    __nv_bfloat16 l0 = __float2bfloat16(v.x - __bfloat162float(h0));
    __nv_bfloat16 l1 = __float2bfloat16(v.y - __bfloat162float(h1));
    __nv_bfloat16 l2 = __float2bfloat16(v.z - __bfloat162float(h2));
    __nv_bfloat16 l3 = __float2bfloat16(v.w - __bfloat162float(h3));
    ((__nv_bfloat162*)Xh)[2*i]   = __nv_bfloat162(h0, h1);
    ((__nv_bfloat162*)Xh)[2*i+1] = __nv_bfloat162(h2, h3);
    ((__nv_bfloat162*)Xl)[2*i]   = __nv_bfloat162(l0, l1);
    ((__nv_bfloat162*)Xl)[2*i+1] = __nv_bfloat162(l2, l3);
}

__global__ void __launch_bounds__(256) split_wT_kernel(
    const float* __restrict__ W, __nv_bfloat16* __restrict__ Th,
    __nv_bfloat16* __restrict__ Tl, int Kdim, int Ndim)
{
    __shared__ float t[32][33];
    int n0 = blockIdx.x * 32, k0 = blockIdx.y * 32;
    int tx = threadIdx.x, ty = threadIdx.y;
    #pragma unroll
    for (int i = ty; i < 32; i += 8)
        t[i][tx] = W[(size_t)(k0 + i) * Ndim + n0 + tx];
    __syncthreads();
    #pragma unroll
    for (int i = ty; i < 32; i += 8) {
        float v = t[tx][i];
        __nv_bfloat16 h = __float2bfloat16(v);
        __nv_bfloat16 l = __float2bfloat16(v - __bfloat162float(h));
        Th[(size_t)(n0 + i) * Kdim + k0 + tx] = h;
        Tl[(size_t)(n0 + i) * Kdim + k0 + tx] = l;
    }
}

// ---------------------------------------------------------------------------
// Pipelined mma.sync split-bf16 GEMM (unchanged from R5/R6)
// ---------------------------------------------------------------------------
#define GK      1024
#define BKC     32
#define NCHUNK  (GK / BKC)
#define PITCH   40
#define TILE_B  (128 * PITCH * 2)
#define STAGE_B (4 * TILE_B)
#define GEMM_SMEM (2 * STAGE_B)

__global__ void __launch_bounds__(256, 2) mma_gemm_kernel(
    const float* __restrict__ bias, float* __restrict__ Cout, int Ntot, int mode)
{
    extern __shared__ char smem[];
    const uint32_t sbase = smem_u32(smem);

    const int tid = threadIdx.x;
    const int wid = tid >> 5, lane = tid & 31;
    const int wm = wid & 3;
    const int wn = wid >> 2;
    const int bx = blockIdx.x, by = blockIdx.y;

    const __nv_bfloat16 *Ah, *Al, *Bh, *Bl;
    if (mode == 0) { Ah = g_xh; Al = g_xl; Bh = g_wqkvT_h; Bl = g_wqkvT_l; }
    else           { Ah = g_oh; Al = g_ol; Bh = g_woT_h;   Bl = g_woT_l;   }

    const size_t aBase = (size_t)(by * 128) * GK;
    const size_t bBase = (size_t)(bx * 128) * GK;

    const int cpr0 = tid >> 2;
    const int cpc0 = (tid & 3) * 8;
    const int cpr1 = (tid + 256) >> 2;
    const int cpc1 = ((tid + 256) & 3) * 8;

    float acc[2][8][4];
    #pragma unroll
    for (int mf = 0; mf < 2; mf++)
        #pragma unroll
        for (int nf = 0; nf < 8; nf++)
            #pragma unroll
            for (int e = 0; e < 4; e++) acc[mf][nf][e] = 0.f;

    const int l7 = lane & 7;
    const int aRowOff = ((lane >> 3) & 1) * 8 + l7;
    const int aKOff   = (lane >> 4) * 8;
    const int bRowOff = ((lane >> 4) & 1) * 8 + l7;
    const int bKOff   = ((lane >> 3) & 1) * 8;

    auto load_stage = [&](int stage, int kc) {
        const int kOff = kc * BKC;
        const uint32_t st = sbase + stage * STAGE_B;
        const __nv_bfloat16* srcs[4] = {
            Ah + aBase + kOff, Al + aBase + kOff,
            Bh + bBase + kOff, Bl + bBase + kOff };
        #pragma unroll
        for (int t = 0; t < 4; t++) {
            const uint32_t dst = st + t * TILE_B;
            cp16(dst + (uint32_t)(cpr0 * PITCH + cpc0) * 2,
                 srcs[t] + (size_t)cpr0 * GK + cpc0);
            cp16(dst + (uint32_t)(cpr1 * PITCH + cpc1) * 2,
                 srcs[t] + (size_t)cpr1 * GK + cpc1);
        }
    };

    load_stage(0, 0);
    CP_COMMIT();

    for (int kc = 0; kc < NCHUNK; kc++) {
        if (kc + 1 < NCHUNK) load_stage((kc + 1) & 1, kc + 1);
        CP_COMMIT();
        CP_WAIT1();
        __syncthreads();

        const uint32_t st = sbase + (kc & 1) * STAGE_B;
        const uint32_t sA_h = st;
        const uint32_t sA_l = st + TILE_B;
        const uint32_t sB_h = st + 2*TILE_B;
        const uint32_t sB_l = st + 3*TILE_B;

        #pragma unroll
        for (int ks = 0; ks < 2; ks++) {
            const int kcol = ks * 16;
            uint32_t ah[2][4], al[2][4];
            #pragma unroll
            for (int mf = 0; mf < 2; mf++) {
                uint32_t off = (uint32_t)((wm*32 + mf*16 + aRowOff) * PITCH
                                          + kcol + aKOff) * 2;
                ldsm_x4(ah[mf][0], ah[mf][1], ah[mf][2], ah[mf][3], sA_h + off);
                ldsm_x4(al[mf][0], al[mf][1], al[mf][2], al[mf][3], sA_l + off);
            }
            #pragma unroll
            for (int nh = 0; nh < 2; nh++) {
                uint32_t bh[4][2], bl[4][2];
                #pragma unroll
                for (int g = 0; g < 2; g++) {
                    uint32_t off = (uint32_t)((wn*64 + nh*32 + g*16 + bRowOff) * PITCH
                                              + kcol + bKOff) * 2;
                    ldsm_x4(bh[g*2][0], bh[g*2][1], bh[g*2+1][0], bh[g*2+1][1],
                            sB_h + off);
                    ldsm_x4(bl[g*2][0], bl[g*2][1], bl[g*2+1][0], bl[g*2+1][1],
                            sB_l + off);
                }
                #pragma unroll
                for (int mf = 0; mf < 2; mf++)
                    #pragma unroll
                    for (int nn = 0; nn < 4; nn++) {
                        float* c = acc[mf][nh*4 + nn];
                        mma_bf16(c[0], c[1], c[2], c[3],
                                 ah[mf][0], ah[mf][1], ah[mf][2], ah[mf][3],
                                 bh[nn][0], bh[nn][1]);
                        mma_bf16(c[0], c[1], c[2], c[3],
                                 ah[mf][0], ah[mf][1], ah[mf][2], ah[mf][3],
                                 bl[nn][0], bl[nn][1]);
                        mma_bf16(c[0], c[1], c[2], c[3],
                                 al[mf][0], al[mf][1], al[mf][2], al[mf][3],
                                 bh[nn][0], bh[nn][1]);
                    }
            }
        }
        __syncthreads();
    }

    const int g = lane >> 2, cq = lane & 3;
    #pragma unroll
    for (int mf = 0; mf < 2; mf++) {
        #pragma unroll
        for (int nf = 0; nf < 8; nf++) {
            const int n = bx*128 + wn*64 + nf*8 + 2*cq;
            const float b0 = bias[n], b1 = bias[n+1];
            #pragma unroll
            for (int half = 0; half < 2; half++) {
                const int m = by*128 + wm*32 + mf*16 + g + half*8;
                float vx = acc[mf][nf][half*2 + 0] + b0;
                float vy = acc[mf][nf][half*2 + 1] + b1;
                if (mode == 0) {
                    __nv_bfloat16 hx = __float2bfloat16(vx);
                    __nv_bfloat16 hy = __float2bfloat16(vy);
                    __nv_bfloat16 lx = __float2bfloat16(vx - __bfloat162float(hx));
                    __nv_bfloat16 ly = __float2bfloat16(vy - __bfloat162float(hy));
                    __nv_bfloat162 h2(hx, hy), l2(lx, ly);
                    const int bb = m >> 11, s = m & 2047;
                    const int h = n / 192;
                    const int rr = n - h * 192;
                    const size_t base = (((size_t)bb * H_ + h) * S_ + s) * HD_;
                    if (rr < 64) {
                        *(__nv_bfloat162*)&g_qh[base + rr] = h2;
                        *(__nv_bfloat162*)&g_ql[base + rr] = l2;
                    } else if (rr < 128) {
                        *(__nv_bfloat162*)&g_kh[base + rr - 64] = h2;
                        *(__nv_bfloat162*)&g_kl[base + rr - 64] = l2;
                    } else {
                        *(__nv_bfloat162*)&g_vh[base + rr - 128] = h2;
                        *(__nv_bfloat162*)&g_vl[base + rr - 128] = l2;
                    }
                } else {
                    float2 v2 = make_float2(vx, vy);
                    *(float2*)&Cout[(size_t)m * Ntot + n] = v2;
                }
            }
        }
    }
}

// ---------------------------------------------------------------------------
// Tensor-core flash attention, cp.async double-buffered K/V streaming.
// Per (head, 64-row qtile), 128 threads = 4 warps, warp = 16 rows.
// ---------------------------------------------------------------------------
#define AP 72                       // smem pitch (elems); conflict-free LDSM
#define ATB (64 * AP * 2)           // 9216 bytes per tile
#define ASTG (4 * ATB)              // stage: Kh,Kl,Vh,Vl
#define ATTN_SMEM (2 * ASTG)        // 73728 bytes

__global__ void __launch_bounds__(128) attn_tc_kernel(float* __restrict__ attn)
{
    const int head = blockIdx.y;
    const int qt   = (int)gridDim.x - 1 - (int)blockIdx.x;

    const __nv_bfloat16* qh = g_qh + (size_t)head * S_ * HD_;
    const __nv_bfloat16* ql = g_ql + (size_t)head * S_ * HD_;
    const __nv_bfloat16* kh = g_kh + (size_t)head * S_ * HD_;
    const __nv_bfloat16* kl = g_kl + (size_t)head * S_ * HD_;
    const __nv_bfloat16* vh = g_vh + (size_t)head * S_ * HD_;
    const __nv_bfloat16* vl = g_vl + (size_t)head * S_ * HD_;
    float* out = attn + (size_t)head * S_ * S_;

    extern __shared__ char dsm[];
    const uint32_t sbase = smem_u32(dsm);

    const int tid = threadIdx.x;
    const int w = tid >> 5, lane = tid & 31;
    const int g = lane >> 2, cq = lane & 3;

    // cp.async chunk assignment: 512 16B chunks per tile, 4 per thread
    const int cpr[4] = { tid >> 3, (tid + 128) >> 3, (tid + 256) >> 3, (tid + 384) >> 3 };
    const int cpc[4] = { (tid & 7) * 8, (tid & 7) * 8, (tid & 7) * 8, (tid & 7) * 8 };

    auto cp_tile = [&](uint32_t dst, const __nv_bfloat16* src) {
        #pragma unroll
        for (int i = 0; i < 4; i++)
            cp16(dst + (uint32_t)(cpr[i] * AP + cpc[i]) * 2,
                 src + (size_t)cpr[i] * HD_ + cpc[i]);
    };
    auto prefetch_K = [&](int stage, int kt) {
        const uint32_t st = sbase + stage * ASTG;
        cp_tile(st,        kh + (size_t)(kt*64) * HD_);
        cp_tile(st + ATB,  kl + (size_t)(kt*64) * HD_);
    };
    auto prefetch_KV = [&](int stage, int kt) {
        const uint32_t st = sbase + stage * ASTG;
        cp_tile(st,          kh + (size_t)(kt*64) * HD_);
        cp_tile(st + ATB,    kl + (size_t)(kt*64) * HD_);
        cp_tile(st + 2*ATB,  vh + (size_t)(kt*64) * HD_);
        cp_tile(st + 3*ATB,  vl + (size_t)(kt*64) * HD_);
    };

    // ---- stage Q via cp.async; zero-fill masked region while in flight ----
    cp_tile(sbase,       qh + (size_t)(qt*64) * HD_);
    cp_tile(sbase + ATB, ql + (size_t)(qt*64) * HD_);
    CP_COMMIT();
    {
        const int c0 = (qt + 1) * 64;
        const int nc = S_ - c0;
        if (nc > 0) {
            const int n4 = nc >> 2;
            const float4 z = make_float4(0.f, 0.f, 0.f, 0.f);
            for (int idx = tid; idx < 64 * n4; idx += 128) {
                int r = idx / n4;
                int c = (idx - r * n4) << 2;
                *(float4*)&out[(size_t)(qt*64 + r)*S_ + c0 + c] = z;
            }
        }
    }
    CP_WAIT0();
    __syncthreads();

    const int l7 = lane & 7;
    const int aRowOff = ((lane >> 3) & 1) * 8 + l7;
    const int aKOff   = (lane >> 4) * 8;
    const int bRowOff = ((lane >> 4) & 1) * 8 + l7;
    const int bKOff   = ((lane >> 3) & 1) * 8;
    const int tRow    = lane & 15;
    const int tCol    = (lane >> 4) * 8;

    uint32_t qfh[4][4], qfl[4][4];
    #pragma unroll
    for (int ks = 0; ks < 4; ks++) {
        uint32_t off = (uint32_t)((w*16 + aRowOff) * AP + ks*16 + aKOff) * 2;
        ldsm_x4(qfh[ks][0], qfh[ks][1], qfh[ks][2], qfh[ks][3], sbase + off);
        ldsm_x4(qfl[ks][0], qfl[ks][1], qfl[ks][2], qfl[ks][3], sbase + ATB + off);
    }
    __syncthreads();

    const int row0 = qt*64 + w*16 + g;
    const int row1 = row0 + 8;
    const float scale = 0.125f;

    float C[8][4];
    auto compute_qk = [&](int kt, uint32_t stKh, uint32_t stKl) {
        #pragma unroll
        for (int f = 0; f < 8; f++)
            #pragma unroll
            for (int e = 0; e < 4; e++) C[f][e] = 0.f;
        #pragma unroll
        for (int ks = 0; ks < 4; ks++) {
            #pragma unroll
            for (int nb = 0; nb < 4; nb++) {
                uint32_t off = (uint32_t)((nb*16 + bRowOff) * AP + ks*16 + bKOff) * 2;
                uint32_t bh0, bh1, bh2, bh3, bl0, bl1, bl2, bl3;
                ldsm_x4(bh0, bh1, bh2, bh3, stKh + off);
                ldsm_x4(bl0, bl1, bl2, bl3, stKl + off);
                float* c0 = C[2*nb];
                float* c1 = C[2*nb + 1];
                mma_bf16(c0[0], c0[1], c0[2], c0[3],
                         qfh[ks][0], qfh[ks][1], qfh[ks][2], qfh[ks][3], bh0, bh1);
                mma_bf16(c0[0], c0[1], c0[2], c0[3],
                         qfh[ks][0], qfh[ks][1], qfh[ks][2], qfh[ks][3], bl0, bl1);
                mma_bf16(c0[0], c0[1], c0[2], c0[3],
                         qfl[ks][0], qfl[ks][1], qfl[ks][2], qfl[ks][3], bh0, bh1);
                mma_bf16(c1[0], c1[1], c1[2], c1[3],
                         qfh[ks][0], qfh[ks][1], qfh[ks][2], qfh[ks][3], bh2, bh3);
                mma_bf16(c1[0], c1[1], c1[2], c1[3],
                         qfh[ks][0], qfh[ks][1], qfh[ks][2], qfh[ks][3], bl2, bl3);
                mma_bf16(c1[0], c1[1], c1[2], c1[3],
                         qfl[ks][0], qfl[ks][1], qfl[ks][2], qfl[ks][3], bh2, bh3);
            }
        }
        const bool diag = (kt == qt);
        #pragma unroll
        for (int f = 0; f < 8; f++) {
            const int cb = kt*64 + f*8 + 2*cq;
            C[f][0] = (diag && cb     > row0) ? -1e30f : C[f][0] * scale;
            C[f][1] = (diag && cb + 1 > row0) ? -1e30f : C[f][1] * scale;
            C[f][2] = (diag && cb     > row1) ? -1e30f : C[f][2] * scale;
            C[f][3] = (diag && cb + 1 > row1) ? -1e30f : C[f][3] * scale;
        }
    };

    // =================== PASS 1: stats only (pipelined K) ===================
    float mrun0 = -INFINITY, mrun1 = -INFINITY, srun0 = 0.f, srun1 = 0.f;
    prefetch_K(0, 0);
    CP_COMMIT();
    for (int kt = 0; kt <= qt; kt++) {
        if (kt < qt) { prefetch_K((kt + 1) & 1, kt + 1); CP_COMMIT(); CP_WAIT1(); }
        else         { CP_WAIT0(); }
        __syncthreads();
        const uint32_t st = sbase + (kt & 1) * ASTG;
        compute_qk(kt, st, st + ATB);

        float t0 = -INFINITY, t1 = -INFINITY;
        #pragma unroll
        for (int f = 0; f < 8; f++) {
            t0 = fmaxf(t0, fmaxf(C[f][0], C[f][1]));
            t1 = fmaxf(t1, fmaxf(C[f][2], C[f][3]));
        }
        #pragma unroll
        for (int o = 1; o <= 2; o <<= 1) {
            t0 = fmaxf(t0, __shfl_xor_sync(0xffffffffu, t0, o));
            t1 = fmaxf(t1, __shfl_xor_sync(0xffffffffu, t1, o));
        }
        const float m0 = fmaxf(mrun0, t0), m1 = fmaxf(mrun1, t1);
        float r0 = 0.f, r1 = 0.f;
        #pragma unroll
        for (int f = 0; f < 8; f++) {
            r0 += __expf(C[f][0] - m0) + __expf(C[f][1] - m0);
            r1 += __expf(C[f][2] - m1) + __expf(C[f][3] - m1);
        }
        #pragma unroll
        for (int o = 1; o <= 2; o <<= 1) {
            r0 += __shfl_xor_sync(0xffffffffu, r0, o);
            r1 += __shfl_xor_sync(0xffffffffu, r1, o);
        }
        srun0 = srun0 * __expf(mrun0 - m0) + r0;  mrun0 = m0;
        srun1 = srun1 * __expf(mrun1 - m1) + r1;  mrun1 = m1;
        __syncthreads();
    }

    const float mf0 = mrun0, mf1 = mrun1;
    const float inv0 = 1.f / srun0, inv1 = 1.f / srun1;

    // =================== PASS 2: probs + AV (pipelined K+V) ===================
    float O[8][4];
    #pragma unroll
    for (int f = 0; f < 8; f++)
        #pragma unroll
        for (int e = 0; e < 4; e++) O[f][e] = 0.f;

    prefetch_KV(0, 0);
    CP_COMMIT();
    for (int kt = 0; kt <= qt; kt++) {
        if (kt < qt) { prefetch_KV((kt + 1) & 1, kt + 1); CP_COMMIT(); CP_WAIT1(); }
        else         { CP_WAIT0(); }
        __syncthreads();
        const uint32_t st = sbase + (kt & 1) * ASTG;
        compute_qk(kt, st, st + ATB);
        const uint32_t aVh = st + 2*ATB;
        const uint32_t aVl = st + 3*ATB;

        #pragma unroll
        for (int f = 0; f < 8; f++) {
            C[f][0] = __expf(C[f][0] - mf0) * inv0;
            C[f][1] = __expf(C[f][1] - mf0) * inv0;
            C[f][2] = __expf(C[f][2] - mf1) * inv1;
            C[f][3] = __expf(C[f][3] - mf1) * inv1;
            const int cb = kt*64 + f*8 + 2*cq;
            *(float2*)&out[(size_t)row0 * S_ + cb] = make_float2(C[f][0], C[f][1]);
            *(float2*)&out[(size_t)row1 * S_ + cb] = make_float2(C[f][2], C[f][3]);
        }

        #pragma unroll
        for (int ks2 = 0; ks2 < 4; ks2++) {
            float p00 = C[2*ks2][0],   p01 = C[2*ks2][1];
            float p02 = C[2*ks2][2],   p03 = C[2*ks2][3];
            float p10 = C[2*ks2+1][0], p11 = C[2*ks2+1][1];
            float p12 = C[2*ks2+1][2], p13 = C[2*ks2+1][3];
            uint32_t ah0 = pack_bf16x2(p00, p01);
            uint32_t ah1 = pack_bf16x2(p02, p03);
            uint32_t ah2 = pack_bf16x2(p10, p11);
            uint32_t ah3 = pack_bf16x2(p12, p13);
            __nv_bfloat162 hh2;
            hh2 = *(__nv_bfloat162*)&ah0;
            uint32_t al0 = pack_bf16x2(p00 - __bfloat162float(hh2.x),
                                       p01 - __bfloat162float(hh2.y));
            hh2 = *(__nv_bfloat162*)&ah1;
            uint32_t al1 = pack_bf16x2(p02 - __bfloat162float(hh2.x),
                                       p03 - __bfloat162float(hh2.y));
            hh2 = *(__nv_bfloat162*)&ah2;
            uint32_t al2 = pack_bf16x2(p10 - __bfloat162float(hh2.x),
                                       p11 - __bfloat162float(hh2.y));
            hh2 = *(__nv_bfloat162*)&ah3;
            uint32_t al3 = pack_bf16x2(p12 - __bfloat162float(hh2.x),
                                       p13 - __bfloat162float(hh2.y));

            #pragma unroll
            for (int dblk = 0; dblk < 4; dblk++) {
                uint32_t off = (uint32_t)((ks2*16 + tRow) * AP + dblk*16 + tCol) * 2;
                uint32_t v0, v1, v2, v3, u0, u1, u2, u3;
                ldsm_x4_t(v0, v1, v2, v3, aVh + off);
                ldsm_x4_t(u0, u1, u2, u3, aVl + off);
                float* o0 = O[2*dblk];
                float* o1 = O[2*dblk + 1];
                mma_bf16(o0[0], o0[1], o0[2], o0[3], ah0, ah1, ah2, ah3, v0, v1);
                mma_bf16(o0[0], o0[1], o0[2], o0[3], al0, al1, al2, al3, v0, v1);
                mma_bf16(o0[0], o0[1], o0[2], o0[3], ah0, ah1, ah2, ah3, u0, u1);
                mma_bf16(o1[0], o1[1], o1[2], o1[3], ah0, ah1, ah2, ah3, v2, v3);
                mma_bf16(o1[0], o1[1], o1[2], o1[3], al0, al1, al2, al3, v2, v3);
                mma_bf16(o1[0], o1[1], o1[2], o1[3], ah0, ah1, ah2, ah3, u2, u3);
            }
        }
        __syncthreads();
    }

    // ---- epilogue: write O as split bf16 to g_oh/g_ol [B,S,E] ----
    const int bb = head >> 4, hh = head & 15;
    #pragma unroll
    for (int f = 0; f < 8; f++) {
        const int e = hh * HD_ + f*8 + 2*cq;
        #pragma unroll
        for (int half = 0; half < 2; half++) {
            const int s = (half == 0) ? row0 : row1;
            float vx = O[f][half*2 + 0], vy = O[f][half*2 + 1];
            __nv_bfloat16 hx = __float2bfloat16(vx);
            __nv_bfloat16 hy = __float2bfloat16(vy);
            __nv_bfloat16 lx = __float2bfloat16(vx - __bfloat162float(hx));
            __nv_bfloat16 ly = __float2bfloat16(vy - __bfloat162float(hy));
            const size_t idx = ((size_t)bb * S_ + s) * E_ + e;
            *(__nv_bfloat162*)&g_oh[idx] = __nv_bfloat162(hx, hy);
            *(__nv_bfloat162*)&g_ol[idx] = __nv_bfloat162(lx, ly);
        }
    }
}

// ---------------------------------------------------------------------------
extern "C" void kernel_launch(void* const* d_in, const int* in_sizes, int n_in,
                              void* d_out, int out_size)
{
    const float* x     = (const float*)d_in[0];
    const float* w_qkv = (const float*)d_in[1];
    const float* b_qkv = (const float*)d_in[2];
    const float* w_o   = (const float*)d_in[3];
    const float* b_o   = (const float*)d_in[4];

    float* o_out    = (float*)d_out;
    float* attn_out = o_out + (size_t)B_ * S_ * E_;

    static bool attr_set = false;
    if (!attr_set) {
        cudaFuncSetAttribute(mma_gemm_kernel,
                             cudaFuncAttributeMaxDynamicSharedMemorySize, GEMM_SMEM);
        cudaFuncSetAttribute(attn_tc_kernel,
                             cudaFuncAttributeMaxDynamicSharedMemorySize, ATTN_SMEM);
        attr_set = true;
    }

    __nv_bfloat16 *p_xh, *p_xl, *p_wqh, *p_wql, *p_woh, *p_wol;
    cudaGetSymbolAddress((void**)&p_xh,  g_xh);
    cudaGetSymbolAddress((void**)&p_xl,  g_xl);
    cudaGetSymbolAddress((void**)&p_wqh, g_wqkvT_h);
    cudaGetSymbolAddress((void**)&p_wql, g_wqkvT_l);
    cudaGetSymbolAddress((void**)&p_woh, g_woT_h);
    cudaGetSymbolAddress((void**)&p_wol, g_woT_l);

    // 0. split inputs to bf16 hi/lo
    {
        int n4 = (MROWS * E_) / 4;
        split_f32_kernel<<<n4 / 256, 256>>>(x, p_xh, p_xl, n4);
        dim3 g1(N3E/32, E_/32);
        split_wT_kernel<<<g1, dim3(32,8)>>>(w_qkv, p_wqh, p_wql, E_, N3E);
        dim3 g2(E_/32, E_/32);
        split_wT_kernel<<<g2, dim3(32,8)>>>(w_o, p_woh, p_wol, E_, E_);
    }
    // 1. QKV projection -> split-bf16 q/k/v
    {
        dim3 grid(N3E/128, MROWS/128);
        mma_gemm_kernel<<<grid, 256, GEMM_SMEM>>>(b_qkv, nullptr, N3E, 0);
    }
    // 2. tensor-core flash attention (pipelined)
    {
        dim3 grid(S_/64, BH_);
        attn_tc_kernel<<<grid, 128, ATTN_SMEM>>>(attn_out);
    }
    // 3. output projection
    {
        dim3 grid(E_/128, MROWS/128);
        mma_gemm_kernel<<<grid, 256, GEMM_SMEM>>>(b_o, o_out, E_, 1);
    }
}